// round 15
// baseline (speedup 1.0000x reference)
#include <cuda_runtime.h>
#include <cuda_fp16.h>
#include <math.h>
#include <stddef.h>

typedef __half h16;

#define B_      256
#define T_      64
#define STOCH   32
#define DETER   1024
#define HIDDEN  1024
#define EMBED   1536
#define ACTD    6
#define ENS     5
#define OUTDIM  1216   // 6*STOCH + DETER

// ---------------- scratch (device globals; no allocation allowed) ----------
__device__ __align__(16) h16 g_WgruH[2048 * 3072];
__device__ __align__(16) h16 g_WgruL[2048 * 3072];
__device__ __align__(16) h16 g_WobsH[2560 * 1024];
__device__ __align__(16) h16 g_WobsL[2560 * 1024];
__device__ __align__(16) h16 g_WensH[ENS * 1024 * 1024];
__device__ __align__(16) h16 g_WensL[ENS * 1024 * 1024];
__device__ __align__(16) h16 g_embF[B_ * T_ * EMBED];
__device__ __align__(16) h16 g_xF[B_ * HIDDEN];
__device__ __align__(16) h16 g_deterF[B_ * DETER];

__device__ __align__(16) float g_pp0a[B_ * 3072];
__device__ __align__(16) float g_pp0b[B_ * 3072];
__device__ __align__(16) float g_pp1[B_ * 3072];
__device__ __align__(16) float g_hp0[B_ * 1024];
__device__ __align__(16) float g_hp1[B_ * 1024];
__device__ __align__(16) float g_xop0a[B_ * 1024];
__device__ __align__(16) float g_xop0b[B_ * 1024];
__device__ __align__(16) float g_xope[B_ * T_ * 1024];  // embed@Wobs, all t
__device__ __align__(16) float g_stoch[B_ * STOCH];
__device__ __align__(16) float g_deter[B_ * DETER];
__device__ __align__(16) float g_WodT[64 * 1024];
__device__ __align__(16) float g_WedT[ENS * 64 * 1024];

// ---------------- fast-math helpers (MUFU; err ~1e-7 rel) -------------------
#define LOG2E 1.4426950408889634f
#define LN2   0.6931471805599453f
__device__ __forceinline__ float fex2(float x) {
    float r; asm("ex2.approx.f32 %0, %1;" : "=f"(r) : "f"(x)); return r;
}
__device__ __forceinline__ float flg2(float x) {
    float r; asm("lg2.approx.f32 %0, %1;" : "=f"(r) : "f"(x)); return r;
}
__device__ __forceinline__ float frcpa(float x) {
    float r; asm("rcp.approx.f32 %0, %1;" : "=f"(r) : "f"(x)); return r;
}
__device__ __forceinline__ float elu1(float x) {
    return x > 0.f ? x : fex2(LOG2E * x) - 1.f;
}
__device__ __forceinline__ float sigm(float x) {
    return frcpa(1.f + fex2(-LOG2E * x));
}
__device__ __forceinline__ float ftanh(float x) {
    float e = fex2(2.f * LOG2E * x);
    return 1.f - 2.f * frcpa(e + 1.f);
}
__device__ __forceinline__ float splus(float x) {
    return fmaxf(x, 0.f) + LN2 * flg2(1.f + fex2(-LOG2E * fabsf(x)));
}

// ---------------- setup kernels ---------------------------------------------
__global__ void k_init() {
    int i = blockIdx.x * blockDim.x + threadIdx.x;
    if (i < B_ * STOCH) g_stoch[i] = 0.f;
    if (i < B_ * DETER) {
        g_deter[i] = 0.f;
        g_deterF[i] = __float2half(0.f);
    }
}

// weights: float -> fp16 hi + fp16 lo(residual)
__global__ void k_split(const float* __restrict__ src, h16* __restrict__ hi,
                        h16* __restrict__ lo, int n) {
    for (int i = blockIdx.x * blockDim.x + threadIdx.x; i < n;
         i += gridDim.x * blockDim.x) {
        float v = src[i];
        h16 h = __float2half(v);
        hi[i] = h;
        lo[i] = __float2half(v - __half2float(h));
    }
}

// activations: float -> single fp16
__global__ void k_cast(const float* __restrict__ src, h16* __restrict__ dst,
                       int n) {
    for (int i = blockIdx.x * blockDim.x + threadIdx.x; i < n;
         i += gridDim.x * blockDim.x)
        dst[i] = __float2half(src[i]);
}

__global__ void k_transpose(const float* __restrict__ Wod,
                            const float* __restrict__ Wed) {
    int i = blockIdx.x * blockDim.x + threadIdx.x;  // 6*65536
    int part = i >> 16;
    int r = i & 65535;
    int j = r >> 10;
    int k = r & 1023;
    if (part == 0) {
        g_WodT[r] = Wod[k * 64 + j];
    } else {
        int h = part - 1;
        g_WedT[(size_t)h * 65536 + r] = Wed[(size_t)h * 65536 + k * 64 + j];
    }
}

// ---------------- prologue: inp for t=0 --------------------------------------
__global__ void k_inp0(const float* __restrict__ action,
                       const unsigned char* __restrict__ is_first,
                       const float* __restrict__ W_inp,
                       const float* __restrict__ b_inp) {
    int b = blockIdx.x;
    int tid = threadIdx.x;
    __shared__ float in[STOCH + ACTD];
    float m = is_first[b * T_] ? 0.f : 1.f;
    if (tid < STOCH)
        in[tid] = 0.f;
    else if (tid < STOCH + ACTD)
        in[tid] = action[(size_t)b * T_ * ACTD + (tid - STOCH)] * m;
    __syncthreads();
    for (int h = tid; h < HIDDEN; h += 256) {
        float s = b_inp[h];
#pragma unroll
        for (int k = 0; k < STOCH + ACTD; k++)
            s = fmaf(in[k], W_inp[k * HIDDEN + h], s);
        g_xF[b * HIDDEN + h] = __float2half(elu1(s));
    }
}

// ---------------- tensor-core fp16 2-term GEMM, flat multi-sub ---------------
struct SubTC {
    const h16* aF; long long lda;
    const h16* wH; const h16* wL; long long ldw;
    int K; int ens;
    const float* bias;
    float* C; long long ldc;
    long long wstride, bstride;
    int mt;                      // M tiles (row tiles) for this sub
};
struct ParamsTC { SubTC s[4]; int start[5]; int nsub; };

__device__ __forceinline__ unsigned saddr(const void* p) {
    return (unsigned)__cvta_generic_to_shared(p);
}
__device__ __forceinline__ void ldsm4(unsigned a, unsigned* r) {
    asm volatile("ldmatrix.sync.aligned.m8n8.x4.shared.b16 {%0,%1,%2,%3}, [%4];"
                 : "=r"(r[0]), "=r"(r[1]), "=r"(r[2]), "=r"(r[3]) : "r"(a));
}
__device__ __forceinline__ void ldsm4t(unsigned a, unsigned* r) {
    asm volatile("ldmatrix.sync.aligned.m8n8.x4.trans.shared.b16 {%0,%1,%2,%3}, [%4];"
                 : "=r"(r[0]), "=r"(r[1]), "=r"(r[2]), "=r"(r[3]) : "r"(a));
}
__device__ __forceinline__ void mma16816(float* c, const unsigned* a,
                                         unsigned b0, unsigned b1) {
    asm volatile(
        "mma.sync.aligned.m16n8k16.row.col.f32.f16.f16.f32 "
        "{%0,%1,%2,%3},{%4,%5,%6,%7},{%8,%9},{%0,%1,%2,%3};"
        : "+f"(c[0]), "+f"(c[1]), "+f"(c[2]), "+f"(c[3])
        : "r"(a[0]), "r"(a[1]), "r"(a[2]), "r"(a[3]), "r"(b0), "r"(b1));
}

__global__ void __launch_bounds__(128) gemm_tc(ParamsTC p,
                                               const int* __restrict__ ens_idx,
                                               int t) {
    const int w = blockIdx.x;
    int si = 0;
#pragma unroll
    for (int i = 1; i < 4; i++)
        if (i < p.nsub && w >= p.start[i]) si = i;
    SubTC s = p.s[si];
    const int r = w - p.start[si];
    const int bm = (r % s.mt) << 6, bn = (r / s.mt) << 6;

    const h16* wH = s.wH;
    const h16* wL = s.wL;
    const float* bias = s.bias;
    if (s.ens) {
        int idx = __ldg(&ens_idx[t]);
        wH += (long long)idx * s.wstride;
        wL += (long long)idx * s.wstride;
        if (bias) bias += (long long)idx * s.bstride;
    }
    const int tid = threadIdx.x, lane = tid & 31, warp = tid >> 5;
    const int warpM = warp & 1, warpN = warp >> 1;

    __shared__ __align__(16) h16 AsF[2][64][32];
    __shared__ __align__(16) h16 BsH[2][32][64], BsL[2][32][64];

    const int ar = tid >> 2, ac = tid & 3;
    const int apc = (ac ^ ((ar >> 1) & 3)) * 8;
    const int br = tid >> 3, bc = tid & 7;
    const int bpc = (bc ^ (br & 7)) * 8;

    const h16* aFp = s.aF + (long long)(bm + ar) * s.lda + ac * 8;
    const h16* wHp = wH + (long long)br * s.ldw + bn + bc * 8;
    const h16* wLp = wL + (long long)br * s.ldw + bn + bc * 8;
    const long long aRowStep = 32 * s.lda;
    const long long bRowStep = 16 * s.ldw;
    const long long bKStep = 32 * s.ldw;

    uint4 pAF0, pAF1, pBH0, pBH1, pBL0, pBL1;
    auto loadStage = [&](int kt) {
        const h16* a = aFp + kt * 32;
        pAF0 = *(const uint4*)a;
        pAF1 = *(const uint4*)(a + aRowStep);
        const h16* b = wHp + (long long)kt * bKStep;
        pBH0 = *(const uint4*)b;
        pBH1 = *(const uint4*)(b + bRowStep);
        const h16* bl = wLp + (long long)kt * bKStep;
        pBL0 = *(const uint4*)bl;
        pBL1 = *(const uint4*)(bl + bRowStep);
    };
    auto storeStage = [&](int bb) {
        *(uint4*)&AsF[bb][ar][apc] = pAF0;
        *(uint4*)&AsF[bb][ar + 32][apc] = pAF1;
        *(uint4*)&BsH[bb][br][bpc] = pBH0;
        *(uint4*)&BsH[bb][br + 16][bpc] = pBH1;
        *(uint4*)&BsL[bb][br][bpc] = pBL0;
        *(uint4*)&BsL[bb][br + 16][bpc] = pBL1;
    };

    float acc[2][4][4] = {};
    const int lrow = lane & 15, lsel = lane >> 4;

    loadStage(0);
    storeStage(0);
    __syncthreads();

    const int nt = s.K >> 5;
    int buf = 0;
    for (int kt = 0; kt < nt; kt++) {
        if (kt + 1 < nt) loadStage(kt + 1);
#pragma unroll
        for (int ks = 0; ks < 2; ks++) {
            unsigned aFf[2][4], bHf[2][4], bLf[2][4];
#pragma unroll
            for (int tm = 0; tm < 2; tm++) {
                int rr = warpM * 32 + tm * 16 + lrow;
                int pc = ((ks * 2 + lsel) ^ ((rr >> 1) & 3)) * 8;
                ldsm4(saddr(&AsF[buf][rr][pc]), aFf[tm]);
            }
            int kr = ks * 16 + lrow;
#pragma unroll
            for (int tn = 0; tn < 2; tn++) {
                int pc = ((warpN * 4 + tn * 2 + lsel) ^ (kr & 7)) * 8;
                ldsm4t(saddr(&BsH[buf][kr][pc]), bHf[tn]);
                ldsm4t(saddr(&BsL[buf][kr][pc]), bLf[tn]);
            }
#pragma unroll
            for (int tm = 0; tm < 2; tm++)
#pragma unroll
                for (int j = 0; j < 4; j++) {
                    unsigned bh0 = bHf[j >> 1][(j & 1) * 2];
                    unsigned bh1 = bHf[j >> 1][(j & 1) * 2 + 1];
                    unsigned bl0 = bLf[j >> 1][(j & 1) * 2];
                    unsigned bl1 = bLf[j >> 1][(j & 1) * 2 + 1];
                    mma16816(acc[tm][j], aFf[tm], bh0, bh1);
                    mma16816(acc[tm][j], aFf[tm], bl0, bl1);
                }
        }
        if (kt + 1 < nt) storeStage(buf ^ 1);
        __syncthreads();
        buf ^= 1;
    }

    const int g = lane >> 2, tg = lane & 3;
#pragma unroll
    for (int tm = 0; tm < 2; tm++) {
        int row = bm + warpM * 32 + tm * 16 + g;
#pragma unroll
        for (int j = 0; j < 4; j++) {
            int col = bn + warpN * 32 + j * 8 + tg * 2;
            float bx = bias ? bias[col] : 0.f;
            float by = bias ? bias[col + 1] : 0.f;
            float2 v0 = { acc[tm][j][0] + bx, acc[tm][j][1] + by };
            float2 v1 = { acc[tm][j][2] + bx, acc[tm][j][3] + by };
            *(float2*)&s.C[(long long)row * s.ldc + col] = v0;
            *(float2*)&s.C[(long long)(row + 8) * s.ldc + col] = v1;
        }
    }
}

// ---------------- gate: masked sum + LayerNorm + GRU update -----------------
__global__ void __launch_bounds__(256) k_gate(const float* __restrict__ ln_g,
                       const float* __restrict__ ln_b,
                       const unsigned char* __restrict__ is_first,
                       float* __restrict__ out, int t) {
    int b = blockIdx.x, tid = threadIdx.x;
    float m = is_first[b * T_ + t] ? 0.f : 1.f;
    const float4* pa4 = (const float4*)(g_pp0a + (size_t)b * 3072);
    const float4* pb4 = (const float4*)(g_pp0b + (size_t)b * 3072);
    const float4* p14 = (const float4*)(g_pp1 + (size_t)b * 3072);

    float4 v[3];
    float s = 0.f, ss = 0.f;
#pragma unroll
    for (int i = 0; i < 3; i++) {
        int ix = tid + i * 256;
        float4 a = pa4[ix], bq = pb4[ix], c = p14[ix];
        float4 vv = { fmaf(m, c.x, a.x + bq.x), fmaf(m, c.y, a.y + bq.y),
                      fmaf(m, c.z, a.z + bq.z), fmaf(m, c.w, a.w + bq.w) };
        v[i] = vv;
        s += vv.x + vv.y + vv.z + vv.w;
        ss = fmaf(vv.x, vv.x, ss); ss = fmaf(vv.y, vv.y, ss);
        ss = fmaf(vv.z, vv.z, ss); ss = fmaf(vv.w, vv.w, ss);
    }
    __shared__ float red[20];
    for (int o = 16; o; o >>= 1) {
        s  += __shfl_down_sync(~0u, s, o);
        ss += __shfl_down_sync(~0u, ss, o);
    }
    if ((tid & 31) == 0) { red[tid >> 5] = s; red[8 + (tid >> 5)] = ss; }
    __syncthreads();
    if (tid == 0) {
        float S = 0.f, SS = 0.f;
        for (int i = 0; i < 8; i++) { S += red[i]; SS += red[8 + i]; }
        float mean = S * (1.f / 3072.f);
        float var  = SS * (1.f / 3072.f) - mean * mean;
        red[16] = mean;
        red[17] = rsqrtf(var + 1e-5f);
    }
    __syncthreads();
    float mean = red[16], rstd = red[17];

    float4 gr = ((const float4*)ln_g)[tid];
    float4 gc = ((const float4*)ln_g)[tid + 256];
    float4 gu = ((const float4*)ln_g)[tid + 512];
    float4 br4 = ((const float4*)ln_b)[tid];
    float4 bc4 = ((const float4*)ln_b)[tid + 256];
    float4 bu4 = ((const float4*)ln_b)[tid + 512];
    float4 dold = ((const float4*)(g_deter + (size_t)b * DETER))[tid];

    float* rr = &v[0].x; float* cc = &v[1].x; float* uu = &v[2].x;
    float* grp = &gr.x; float* gcp = &gc.x; float* gup = &gu.x;
    float* brp = &br4.x; float* bcp = &bc4.x; float* bup = &bu4.x;
    float* dop = &dold.x;

    float4 dnew;
    float* dnp = &dnew.x;
    unsigned short fvs[4];
#pragma unroll
    for (int j = 0; j < 4; j++) {
        float r = (rr[j] - mean) * rstd * grp[j] + brp[j];
        float c = (cc[j] - mean) * rstd * gcp[j] + bcp[j];
        float u = (uu[j] - mean) * rstd * gup[j] + bup[j];
        float reset  = sigm(r);
        float cand   = ftanh(reset * c);
        float update = sigm(u - 1.0f);
        float dn = update * cand + (1.f - update) * (m * dop[j]);
        dnp[j] = dn;
        h16 fv = __float2half(dn);
        fvs[j] = *(unsigned short*)&fv;
    }
    ((float4*)(g_deter + (size_t)b * DETER))[tid] = dnew;
    *(uint2*)&g_deterF[(size_t)b * DETER + 4 * tid] = *(uint2*)fvs;
    float* orow = out + ((size_t)b * T_ + t) * OUTDIM + 192;
    *(float4*)&orow[4 * tid] = dnew;
}

// ---------------- posterior dist (2 batches/CTA) + fused inp(t+1) -----------
__global__ void __launch_bounds__(256) k_post_inp(
                           const float* __restrict__ eps_post,
                           const float* __restrict__ bod,
                           float* __restrict__ out,
                           const float* __restrict__ action,
                           const unsigned char* __restrict__ is_first,
                           const float* __restrict__ W_inp,
                           const float* __restrict__ b_inp,
                           int t, int last) {
    const int b0 = blockIdx.x;           // handles b0 and b0+128
    const int tid = threadIdx.x;
    const int lane = tid & 31, wid = tid >> 5;

    __shared__ __align__(16) float sh[2048];   // [2][1024] xo
    __shared__ float sval[128];                // [2][64]
    __shared__ float spost[64];
    __shared__ float sin2[2][40];

    float4* sh4 = (float4*)sh;
#pragma unroll
    for (int ib = 0; ib < 2; ib++) {
        int b = b0 + ib * 128;
        const float4* xa = (const float4*)(g_xop0a + (size_t)b * 1024);
        const float4* xb = (const float4*)(g_xop0b + (size_t)b * 1024);
        const float4* xe = (const float4*)(g_xope + ((size_t)b * T_ + t) * 1024);
        float4 p = xa[tid], r = xb[tid], q = xe[tid];
        float4 f = { elu1(p.x + r.x + q.x), elu1(p.y + r.y + q.y),
                     elu1(p.z + r.z + q.z), elu1(p.w + r.w + q.w) };
        sh4[ib * 256 + tid] = f;
    }
    __syncthreads();

    for (int oo = wid; oo < 64; oo += 8) {
        const float4* w4 = (const float4*)(g_WodT + oo * 1024);
        const float4* a4 = (const float4*)sh;
        const float4* b4 = (const float4*)(sh + 1024);
        float s0 = 0.f, s1 = 0.f;
#pragma unroll
        for (int k = lane; k < 256; k += 32) {
            float4 w = w4[k], a = a4[k], b = b4[k];
            s0 += w.x * a.x + w.y * a.y + w.z * a.z + w.w * a.w;
            s1 += w.x * b.x + w.y * b.y + w.z * b.z + w.w * b.w;
        }
        for (int off = 16; off; off >>= 1) {
            s0 += __shfl_down_sync(~0u, s0, off);
            s1 += __shfl_down_sync(~0u, s1, off);
        }
        if (lane == 0) {
            float bb = bod[oo];
            sval[oo] = s0 + bb;
            sval[64 + oo] = s1 + bb;
        }
    }
    __syncthreads();

    if (tid < 64) {
        int ib = tid >> 5, j = tid & 31;
        int b = b0 + ib * 128;
        const float* sv = sval + ib * 64;
        float* orow = out + ((size_t)b * T_ + t) * OUTDIM;
        float om = sv[j];
        float os = splus(sv[32 + j]) + 0.1f;
        float eq = eps_post[((size_t)b * T_ + t) * STOCH + j];
        float post = fmaf(os, eq, om);
        orow[j]      = om;
        orow[32 + j] = os;
        orow[64 + j] = post;
        spost[ib * 32 + j] = post;
    }
    if (last) return;
    __syncthreads();

    // fused inp(t+1)
    if (tid < 38) {
        float m = is_first[b0 * T_ + t + 1] ? 0.f : 1.f;
        sin2[0][tid] = (tid < 32 ? spost[tid]
                        : action[((size_t)b0 * T_ + t + 1) * ACTD + tid - 32]) * m;
    } else if (tid < 76) {
        int j = tid - 38;
        int b1 = b0 + 128;
        float m = is_first[b1 * T_ + t + 1] ? 0.f : 1.f;
        sin2[1][j] = (j < 32 ? spost[32 + j]
                      : action[((size_t)b1 * T_ + t + 1) * ACTD + j - 32]) * m;
    }
    __syncthreads();
#pragma unroll
    for (int hh = 0; hh < 4; hh++) {
        int h = tid + hh * 256;
        float s0 = b_inp[h], s1 = s0;
#pragma unroll
        for (int k = 0; k < STOCH + ACTD; k++) {
            float w = W_inp[k * HIDDEN + h];
            s0 = fmaf(sin2[0][k], w, s0);
            s1 = fmaf(sin2[1][k], w, s1);
        }
        g_xF[b0 * HIDDEN + h] = __float2half(elu1(s0));
        g_xF[(b0 + 128) * HIDDEN + h] = __float2half(elu1(s1));
    }
}

// ---------------- prior dist (2 batches/CTA), background stream -------------
__global__ void __launch_bounds__(256) k_prior(
                        const float* __restrict__ eps_prior,
                        const int* __restrict__ ens_idx,
                        const float* __restrict__ bed,
                        float* __restrict__ out, int t) {
    const int b0 = blockIdx.x;
    const int tid = threadIdx.x;
    const int lane = tid & 31, wid = tid >> 5;
    const int idx = __ldg(&ens_idx[t]);

    __shared__ __align__(16) float sh[2048];   // [2][1024] h
    __shared__ float sval[128];

    float4* sh4 = (float4*)sh;
#pragma unroll
    for (int ib = 0; ib < 2; ib++) {
        int b = b0 + ib * 128;
        const float4* h0 = (const float4*)(g_hp0 + (size_t)b * 1024);
        const float4* h1 = (const float4*)(g_hp1 + (size_t)b * 1024);
        float4 a = h0[tid], c = h1[tid];
        float4 e = { elu1(a.x + c.x), elu1(a.y + c.y),
                     elu1(a.z + c.z), elu1(a.w + c.w) };
        sh4[ib * 256 + tid] = e;
    }
    __syncthreads();

    for (int oo = wid; oo < 64; oo += 8) {
        const float4* w4 = (const float4*)(g_WedT + (size_t)idx * 65536 + oo * 1024);
        const float4* a4 = (const float4*)sh;
        const float4* b4 = (const float4*)(sh + 1024);
        float s0 = 0.f, s1 = 0.f;
#pragma unroll
        for (int k = lane; k < 256; k += 32) {
            float4 w = w4[k], a = a4[k], b = b4[k];
            s0 += w.x * a.x + w.y * a.y + w.z * a.z + w.w * a.w;
            s1 += w.x * b.x + w.y * b.y + w.z * b.z + w.w * b.w;
        }
        for (int off = 16; off; off >>= 1) {
            s0 += __shfl_down_sync(~0u, s0, off);
            s1 += __shfl_down_sync(~0u, s1, off);
        }
        if (lane == 0) {
            float bb = bed[idx * 64 + oo];
            sval[oo] = s0 + bb;
            sval[64 + oo] = s1 + bb;
        }
    }
    __syncthreads();

    if (tid < 64) {
        int ib = tid >> 5, j = tid & 31;
        int b = b0 + ib * 128;
        const float* sv = sval + ib * 64;
        float* orow = out + ((size_t)b * T_ + t) * OUTDIM;
        float pm = sv[j];
        float ps = splus(sv[32 + j]) + 0.1f;
        float ep = eps_prior[((size_t)b * T_ + t) * STOCH + j];
        float prior = fmaf(ps, ep, pm);
        orow[96 + j]  = pm;
        orow[128 + j] = ps;
        orow[160 + j] = prior;
    }
}

// ---------------- launch ----------------------------------------------------
extern "C" void kernel_launch(void* const* d_in, const int* in_sizes, int n_in,
                              void* d_out, int out_size) {
    const float* embed      = (const float*)d_in[0];
    const float* action     = (const float*)d_in[1];
    const float* eps_post   = (const float*)d_in[2];
    const float* eps_prior  = (const float*)d_in[3];
    const unsigned char* is_first = (const unsigned char*)d_in[4];
    const int*   ens_idx    = (const int*)d_in[5];
    const float* W_gru      = (const float*)d_in[6];
    const float* b_gru      = (const float*)d_in[7];
    const float* ln_g       = (const float*)d_in[8];
    const float* ln_b       = (const float*)d_in[9];
    const float* W_inp      = (const float*)d_in[10];
    const float* b_inp      = (const float*)d_in[11];
    const float* W_obs      = (const float*)d_in[12];
    const float* b_obs      = (const float*)d_in[13];
    const float* W_ens      = (const float*)d_in[14];
    const float* b_ens      = (const float*)d_in[15];
    const float* W_obs_dist = (const float*)d_in[16];
    const float* b_obs_dist = (const float*)d_in[17];
    const float* W_ens_dist = (const float*)d_in[18];
    const float* b_ens_dist = (const float*)d_in[19];
    float* out = (float*)d_out;

    h16 *wgH, *wgL, *woH, *woL, *weH, *weL, *emF, *xF, *dF;
    float *ppa, *ppb, *pp1, *php0, *php1, *pxa, *pxb, *pxope;
    cudaGetSymbolAddress((void**)&wgH, g_WgruH);
    cudaGetSymbolAddress((void**)&wgL, g_WgruL);
    cudaGetSymbolAddress((void**)&woH, g_WobsH);
    cudaGetSymbolAddress((void**)&woL, g_WobsL);
    cudaGetSymbolAddress((void**)&weH, g_WensH);
    cudaGetSymbolAddress((void**)&weL, g_WensL);
    cudaGetSymbolAddress((void**)&emF, g_embF);
    cudaGetSymbolAddress((void**)&xF,  g_xF);
    cudaGetSymbolAddress((void**)&dF,  g_deterF);
    cudaGetSymbolAddress((void**)&ppa, g_pp0a);
    cudaGetSymbolAddress((void**)&ppb, g_pp0b);
    cudaGetSymbolAddress((void**)&pp1, g_pp1);
    cudaGetSymbolAddress((void**)&php0, g_hp0);
    cudaGetSymbolAddress((void**)&php1, g_hp1);
    cudaGetSymbolAddress((void**)&pxa, g_xop0a);
    cudaGetSymbolAddress((void**)&pxb, g_xop0b);
    cudaGetSymbolAddress((void**)&pxope, g_xope);

    // persistent streams/events (host objects, created once)
    static cudaStream_t s2 = 0, s3 = 0;
    static cudaEvent_t e0 = 0, eW = 0, eEmb = 0, eTr = 0, eGate = 0,
                       eBg = 0, eFin = 0;
    if (!s2) {
        int lo = 0, hi = 0;
        cudaDeviceGetStreamPriorityRange(&lo, &hi);
        cudaStreamCreateWithPriority(&s2, cudaStreamNonBlocking, lo);
        cudaStreamCreateWithPriority(&s3, cudaStreamNonBlocking, lo);
        cudaEventCreateWithFlags(&e0,    cudaEventDisableTiming);
        cudaEventCreateWithFlags(&eW,    cudaEventDisableTiming);
        cudaEventCreateWithFlags(&eEmb,  cudaEventDisableTiming);
        cudaEventCreateWithFlags(&eTr,   cudaEventDisableTiming);
        cudaEventCreateWithFlags(&eGate, cudaEventDisableTiming);
        cudaEventCreateWithFlags(&eBg,   cudaEventDisableTiming);
        cudaEventCreateWithFlags(&eFin,  cudaEventDisableTiming);
    }

    // common subs
    SubTC subGruXa = { xF, HIDDEN, wgH, wgL, 3072, 512, 0,
                       b_gru, ppa, 3072, 0, 0, 4 };
    SubTC subGruXb = { xF + 512, HIDDEN,
                       wgH + (size_t)512 * 3072, wgL + (size_t)512 * 3072,
                       3072, 512, 0, nullptr, ppb, 3072, 0, 0, 4 };
    SubTC subGruD  = { dF, DETER, wgH + (size_t)1024 * 3072,
                       wgL + (size_t)1024 * 3072, 3072, 1024, 0,
                       nullptr, pp1, 3072, 0, 0, 4 };
    SubTC subEns0 = { dF, DETER, weH, weL, 1024, 512, 1,
                      b_ens, php0, 1024, (long long)DETER * HIDDEN, HIDDEN, 4 };
    SubTC subEns1 = { dF + 512, DETER,
                      weH + (size_t)512 * 1024, weL + (size_t)512 * 1024,
                      1024, 512, 1,
                      nullptr, php1, 1024, (long long)DETER * HIDDEN, HIDDEN, 4 };
    SubTC subObsDa = { dF, DETER, woH, woL, 1024, 512, 0,
                       b_obs, pxa, 1024, 0, 0, 4 };
    SubTC subObsDb = { dF + 512, DETER,
                       woH + (size_t)512 * 1024, woL + (size_t)512 * 1024,
                       1024, 512, 0, nullptr, pxb, 1024, 0, 0, 4 };

    // ---- setup: stream 0 ----
    k_init<<<(B_ * DETER + 255) / 256, 256>>>();
    cudaEventRecord(e0, 0);
    k_split<<<4096, 256>>>(W_obs, woH, woL, 2560 * 1024);
    cudaEventRecord(eW, 0);
    k_split<<<4096, 256>>>(W_gru, wgH, wgL, 2048 * 3072);
    k_transpose<<<(6 * 65536) / 256, 256>>>(W_obs_dist, W_ens_dist);
    cudaEventRecord(eTr, 0);
    k_inp0<<<B_, 256>>>(action, is_first, W_inp, b_inp);

    // prologue: full GRU GEMM for t=0
    {
        ParamsTC p = {};
        p.s[0] = subGruXa;
        p.s[1] = subGruXb;
        p.s[2] = subGruD;
        p.start[0] = 0; p.start[1] = 192; p.start[2] = 384; p.start[3] = 576;
        p.nsub = 3;
        gemm_tc<<<576, 128>>>(p, ens_idx, 0);
    }

    // ---- s2: embed cast + xope GEMM (setup only) ----
    cudaStreamWaitEvent(s2, e0, 0);
    k_cast<<<8192, 256, 0, s2>>>(embed, emF, B_ * T_ * EMBED);
    cudaStreamWaitEvent(s2, eW, 0);
    {
        ParamsTC p = {};
        p.s[0] = { emF, EMBED,
                   woH + (size_t)1024 * 1024, woL + (size_t)1024 * 1024, 1024,
                   1536, 0, nullptr, pxope, 1024, 0, 0, 256 };
        p.start[0] = 0; p.start[1] = 4096;
        p.nsub = 1;
        gemm_tc<<<4096, 128, 0, s2>>>(p, ens_idx, 0);
    }
    cudaEventRecord(eEmb, s2);

    // ---- s3: Wens split + per-step background ----
    cudaStreamWaitEvent(s3, e0, 0);
    k_split<<<4096, 256, 0, s3>>>(W_ens, weH, weL, ENS * 1024 * 1024);
    cudaStreamWaitEvent(s3, eTr, 0);   // prior needs WedT

    // xope ready before the loop
    cudaStreamWaitEvent(0, eEmb, 0);

    for (int t = 0; t < T_; t++) {
        // gate(t) — needs pp0a/pp0b (main) and pp1 (bg, joined via eBg)
        k_gate<<<B_, 256>>>(ln_g, ln_b, is_first, out, t);
        cudaEventRecord(eGate, 0);

        // background (s3): ens(t) [+ gruD(t+1)] GEMM, then prior dist(t)
        cudaStreamWaitEvent(s3, eGate, 0);
        {
            ParamsTC p = {};
            p.s[0] = subEns0;
            p.s[1] = subEns1;
            p.start[0] = 0; p.start[1] = 64; p.start[2] = 128;
            p.nsub = 2;
            int grid = 128;
            if (t + 1 < T_) {
                p.s[2] = subGruD;
                p.start[3] = 320;
                p.nsub = 3;
                grid = 320;
            }
            gemm_tc<<<grid, 128, 0, s3>>>(p, ens_idx, t);
        }
        cudaEventRecord(eBg, s3);
        k_prior<<<B_ / 2, 256, 0, s3>>>(eps_prior, ens_idx, b_ens_dist, out, t);

        // critical: obs-deter GEMM, split-K (128 tiles)
        {
            ParamsTC p = {};
            p.s[0] = subObsDa;
            p.s[1] = subObsDb;
            p.start[0] = 0; p.start[1] = 64; p.start[2] = 128;
            p.nsub = 2;
            gemm_tc<<<128, 128>>>(p, ens_idx, t);
        }

        // posterior + fused inp(t+1)
        k_post_inp<<<B_ / 2, 256>>>(eps_post, b_obs_dist, out,
                                    action, is_first, W_inp, b_inp,
                                    t, t + 1 == T_);

        if (t + 1 < T_) {
            ParamsTC p = {};
            p.s[0] = subGruXa;
            p.s[1] = subGruXb;
            p.start[0] = 0; p.start[1] = 192; p.start[2] = 384;
            p.nsub = 2;
            gemm_tc<<<384, 128>>>(p, ens_idx, t + 1);
            cudaStreamWaitEvent(0, eBg, 0);   // pp1 ready before gate(t+1)
        }
    }

    // final join: all background work before harness reads
    cudaEventRecord(eFin, s3);
    cudaStreamWaitEvent(0, eFin, 0);
}

// round 16
// speedup vs baseline: 1.1318x; 1.1318x over previous
#include <cuda_runtime.h>
#include <cuda_fp16.h>
#include <math.h>
#include <stddef.h>

typedef __half h16;

#define B_      256
#define T_      64
#define STOCH   32
#define DETER   1024
#define HIDDEN  1024
#define EMBED   1536
#define ACTD    6
#define ENS     5
#define OUTDIM  1216   // 6*STOCH + DETER

// ---------------- scratch (device globals; no allocation allowed) ----------
__device__ __align__(16) h16 g_WgruH[2048 * 3072];
__device__ __align__(16) h16 g_WgruL[2048 * 3072];
__device__ __align__(16) h16 g_WobsH[2560 * 1024];
__device__ __align__(16) h16 g_WobsL[2560 * 1024];
__device__ __align__(16) h16 g_WensH[ENS * 1024 * 1024];
__device__ __align__(16) h16 g_WensL[ENS * 1024 * 1024];
__device__ __align__(16) h16 g_embF[B_ * T_ * EMBED];
__device__ __align__(16) h16 g_xF[B_ * HIDDEN];
__device__ __align__(16) h16 g_deterF[B_ * DETER];

__device__ __align__(16) float g_pp0a[B_ * 3072];
__device__ __align__(16) float g_pp0b[B_ * 3072];
__device__ __align__(16) float g_pp1[B_ * 3072];
__device__ __align__(16) float g_hp0[B_ * 1024];
__device__ __align__(16) float g_hp1[B_ * 1024];
__device__ __align__(16) float g_xop0a[B_ * 1024];
__device__ __align__(16) float g_xop0b[B_ * 1024];
__device__ __align__(16) float g_xope[B_ * T_ * 1024];  // embed@Wobs, all t
__device__ __align__(16) float g_stoch[B_ * STOCH];
__device__ __align__(16) float g_deter[B_ * DETER];
__device__ __align__(16) float g_WodT[64 * 1024];
__device__ __align__(16) float g_WedT[ENS * 64 * 1024];

// ---------------- fast-math helpers (MUFU; err ~1e-7 rel) -------------------
#define LOG2E 1.4426950408889634f
#define LN2   0.6931471805599453f
__device__ __forceinline__ float fex2(float x) {
    float r; asm("ex2.approx.f32 %0, %1;" : "=f"(r) : "f"(x)); return r;
}
__device__ __forceinline__ float flg2(float x) {
    float r; asm("lg2.approx.f32 %0, %1;" : "=f"(r) : "f"(x)); return r;
}
__device__ __forceinline__ float frcpa(float x) {
    float r; asm("rcp.approx.f32 %0, %1;" : "=f"(r) : "f"(x)); return r;
}
__device__ __forceinline__ float elu1(float x) {
    return x > 0.f ? x : fex2(LOG2E * x) - 1.f;
}
__device__ __forceinline__ float sigm(float x) {
    return frcpa(1.f + fex2(-LOG2E * x));
}
__device__ __forceinline__ float ftanh(float x) {
    float e = fex2(2.f * LOG2E * x);
    return 1.f - 2.f * frcpa(e + 1.f);
}
__device__ __forceinline__ float splus(float x) {
    return fmaxf(x, 0.f) + LN2 * flg2(1.f + fex2(-LOG2E * fabsf(x)));
}

// ---------------- setup kernels ---------------------------------------------
__global__ void k_init() {
    int i = blockIdx.x * blockDim.x + threadIdx.x;
    if (i < B_ * STOCH) g_stoch[i] = 0.f;
    if (i < B_ * DETER) {
        g_deter[i] = 0.f;
        g_deterF[i] = __float2half(0.f);
    }
}

// weights: float -> fp16 hi + fp16 lo(residual)
__global__ void k_split(const float* __restrict__ src, h16* __restrict__ hi,
                        h16* __restrict__ lo, int n) {
    for (int i = blockIdx.x * blockDim.x + threadIdx.x; i < n;
         i += gridDim.x * blockDim.x) {
        float v = src[i];
        h16 h = __float2half(v);
        hi[i] = h;
        lo[i] = __float2half(v - __half2float(h));
    }
}

// activations: float -> single fp16
__global__ void k_cast(const float* __restrict__ src, h16* __restrict__ dst,
                       int n) {
    for (int i = blockIdx.x * blockDim.x + threadIdx.x; i < n;
         i += gridDim.x * blockDim.x)
        dst[i] = __float2half(src[i]);
}

__global__ void k_transpose(const float* __restrict__ Wod,
                            const float* __restrict__ Wed) {
    int i = blockIdx.x * blockDim.x + threadIdx.x;  // 6*65536
    int part = i >> 16;
    int r = i & 65535;
    int j = r >> 10;
    int k = r & 1023;
    if (part == 0) {
        g_WodT[r] = Wod[k * 64 + j];
    } else {
        int h = part - 1;
        g_WedT[(size_t)h * 65536 + r] = Wed[(size_t)h * 65536 + k * 64 + j];
    }
}

// ---------------- prologue: inp for t=0 --------------------------------------
__global__ void k_inp0(const float* __restrict__ action,
                       const unsigned char* __restrict__ is_first,
                       const float* __restrict__ W_inp,
                       const float* __restrict__ b_inp) {
    int b = blockIdx.x;
    int tid = threadIdx.x;
    __shared__ float in[STOCH + ACTD];
    float m = is_first[b * T_] ? 0.f : 1.f;
    if (tid < STOCH)
        in[tid] = 0.f;
    else if (tid < STOCH + ACTD)
        in[tid] = action[(size_t)b * T_ * ACTD + (tid - STOCH)] * m;
    __syncthreads();
    for (int h = tid; h < HIDDEN; h += 256) {
        float s = b_inp[h];
#pragma unroll
        for (int k = 0; k < STOCH + ACTD; k++)
            s = fmaf(in[k], W_inp[k * HIDDEN + h], s);
        g_xF[b * HIDDEN + h] = __float2half(elu1(s));
    }
}

// ---------------- tensor-core fp16 2-term GEMM, flat multi-sub ---------------
struct SubTC {
    const h16* aF; long long lda;
    const h16* wH; const h16* wL; long long ldw;
    int K; int ens;
    const float* bias;
    float* C; long long ldc;
    long long wstride, bstride;
    int mt;                      // M tiles (row tiles) for this sub
};
struct ParamsTC { SubTC s[4]; int start[5]; int nsub; };

__device__ __forceinline__ unsigned saddr(const void* p) {
    return (unsigned)__cvta_generic_to_shared(p);
}
__device__ __forceinline__ void ldsm4(unsigned a, unsigned* r) {
    asm volatile("ldmatrix.sync.aligned.m8n8.x4.shared.b16 {%0,%1,%2,%3}, [%4];"
                 : "=r"(r[0]), "=r"(r[1]), "=r"(r[2]), "=r"(r[3]) : "r"(a));
}
__device__ __forceinline__ void ldsm4t(unsigned a, unsigned* r) {
    asm volatile("ldmatrix.sync.aligned.m8n8.x4.trans.shared.b16 {%0,%1,%2,%3}, [%4];"
                 : "=r"(r[0]), "=r"(r[1]), "=r"(r[2]), "=r"(r[3]) : "r"(a));
}
__device__ __forceinline__ void mma16816(float* c, const unsigned* a,
                                         unsigned b0, unsigned b1) {
    asm volatile(
        "mma.sync.aligned.m16n8k16.row.col.f32.f16.f16.f32 "
        "{%0,%1,%2,%3},{%4,%5,%6,%7},{%8,%9},{%0,%1,%2,%3};"
        : "+f"(c[0]), "+f"(c[1]), "+f"(c[2]), "+f"(c[3])
        : "r"(a[0]), "r"(a[1]), "r"(a[2]), "r"(a[3]), "r"(b0), "r"(b1));
}

__global__ void __launch_bounds__(128) gemm_tc(ParamsTC p,
                                               const int* __restrict__ ens_idx,
                                               int t) {
    const int w = blockIdx.x;
    int si = 0;
#pragma unroll
    for (int i = 1; i < 4; i++)
        if (i < p.nsub && w >= p.start[i]) si = i;
    SubTC s = p.s[si];
    const int r = w - p.start[si];
    const int bm = (r % s.mt) << 6, bn = (r / s.mt) << 6;

    const h16* wH = s.wH;
    const h16* wL = s.wL;
    const float* bias = s.bias;
    if (s.ens) {
        int idx = __ldg(&ens_idx[t]);
        wH += (long long)idx * s.wstride;
        wL += (long long)idx * s.wstride;
        if (bias) bias += (long long)idx * s.bstride;
    }
    const int tid = threadIdx.x, lane = tid & 31, warp = tid >> 5;
    const int warpM = warp & 1, warpN = warp >> 1;

    __shared__ __align__(16) h16 AsF[2][64][32];
    __shared__ __align__(16) h16 BsH[2][32][64], BsL[2][32][64];

    const int ar = tid >> 2, ac = tid & 3;
    const int apc = (ac ^ ((ar >> 1) & 3)) * 8;
    const int br = tid >> 3, bc = tid & 7;
    const int bpc = (bc ^ (br & 7)) * 8;

    const h16* aFp = s.aF + (long long)(bm + ar) * s.lda + ac * 8;
    const h16* wHp = wH + (long long)br * s.ldw + bn + bc * 8;
    const h16* wLp = wL + (long long)br * s.ldw + bn + bc * 8;
    const long long aRowStep = 32 * s.lda;
    const long long bRowStep = 16 * s.ldw;
    const long long bKStep = 32 * s.ldw;

    uint4 pAF0, pAF1, pBH0, pBH1, pBL0, pBL1;
    auto loadStage = [&](int kt) {
        const h16* a = aFp + kt * 32;
        pAF0 = *(const uint4*)a;
        pAF1 = *(const uint4*)(a + aRowStep);
        const h16* b = wHp + (long long)kt * bKStep;
        pBH0 = *(const uint4*)b;
        pBH1 = *(const uint4*)(b + bRowStep);
        const h16* bl = wLp + (long long)kt * bKStep;
        pBL0 = *(const uint4*)bl;
        pBL1 = *(const uint4*)(bl + bRowStep);
    };
    auto storeStage = [&](int bb) {
        *(uint4*)&AsF[bb][ar][apc] = pAF0;
        *(uint4*)&AsF[bb][ar + 32][apc] = pAF1;
        *(uint4*)&BsH[bb][br][bpc] = pBH0;
        *(uint4*)&BsH[bb][br + 16][bpc] = pBH1;
        *(uint4*)&BsL[bb][br][bpc] = pBL0;
        *(uint4*)&BsL[bb][br + 16][bpc] = pBL1;
    };

    float acc[2][4][4] = {};
    const int lrow = lane & 15, lsel = lane >> 4;

    loadStage(0);
    storeStage(0);
    __syncthreads();

    const int nt = s.K >> 5;
    int buf = 0;
    for (int kt = 0; kt < nt; kt++) {
        if (kt + 1 < nt) loadStage(kt + 1);
#pragma unroll
        for (int ks = 0; ks < 2; ks++) {
            unsigned aFf[2][4], bHf[2][4], bLf[2][4];
#pragma unroll
            for (int tm = 0; tm < 2; tm++) {
                int rr = warpM * 32 + tm * 16 + lrow;
                int pc = ((ks * 2 + lsel) ^ ((rr >> 1) & 3)) * 8;
                ldsm4(saddr(&AsF[buf][rr][pc]), aFf[tm]);
            }
            int kr = ks * 16 + lrow;
#pragma unroll
            for (int tn = 0; tn < 2; tn++) {
                int pc = ((warpN * 4 + tn * 2 + lsel) ^ (kr & 7)) * 8;
                ldsm4t(saddr(&BsH[buf][kr][pc]), bHf[tn]);
                ldsm4t(saddr(&BsL[buf][kr][pc]), bLf[tn]);
            }
#pragma unroll
            for (int tm = 0; tm < 2; tm++)
#pragma unroll
                for (int j = 0; j < 4; j++) {
                    unsigned bh0 = bHf[j >> 1][(j & 1) * 2];
                    unsigned bh1 = bHf[j >> 1][(j & 1) * 2 + 1];
                    unsigned bl0 = bLf[j >> 1][(j & 1) * 2];
                    unsigned bl1 = bLf[j >> 1][(j & 1) * 2 + 1];
                    mma16816(acc[tm][j], aFf[tm], bh0, bh1);
                    mma16816(acc[tm][j], aFf[tm], bl0, bl1);
                }
        }
        if (kt + 1 < nt) storeStage(buf ^ 1);
        __syncthreads();
        buf ^= 1;
    }

    const int g = lane >> 2, tg = lane & 3;
#pragma unroll
    for (int tm = 0; tm < 2; tm++) {
        int row = bm + warpM * 32 + tm * 16 + g;
#pragma unroll
        for (int j = 0; j < 4; j++) {
            int col = bn + warpN * 32 + j * 8 + tg * 2;
            float bx = bias ? bias[col] : 0.f;
            float by = bias ? bias[col + 1] : 0.f;
            float2 v0 = { acc[tm][j][0] + bx, acc[tm][j][1] + by };
            float2 v1 = { acc[tm][j][2] + bx, acc[tm][j][3] + by };
            *(float2*)&s.C[(long long)row * s.ldc + col] = v0;
            *(float2*)&s.C[(long long)(row + 8) * s.ldc + col] = v1;
        }
    }
}

// ---------------- gate: masked sum + LayerNorm + GRU update -----------------
__global__ void __launch_bounds__(256) k_gate(const float* __restrict__ ln_g,
                       const float* __restrict__ ln_b,
                       const unsigned char* __restrict__ is_first,
                       float* __restrict__ out, int t) {
    int b = blockIdx.x, tid = threadIdx.x;
    float m = is_first[b * T_ + t] ? 0.f : 1.f;
    const float4* pa4 = (const float4*)(g_pp0a + (size_t)b * 3072);
    const float4* pb4 = (const float4*)(g_pp0b + (size_t)b * 3072);
    const float4* p14 = (const float4*)(g_pp1 + (size_t)b * 3072);

    float4 v[3];
    float s = 0.f, ss = 0.f;
#pragma unroll
    for (int i = 0; i < 3; i++) {
        int ix = tid + i * 256;
        float4 a = pa4[ix], bq = pb4[ix], c = p14[ix];
        float4 vv = { fmaf(m, c.x, a.x + bq.x), fmaf(m, c.y, a.y + bq.y),
                      fmaf(m, c.z, a.z + bq.z), fmaf(m, c.w, a.w + bq.w) };
        v[i] = vv;
        s += vv.x + vv.y + vv.z + vv.w;
        ss = fmaf(vv.x, vv.x, ss); ss = fmaf(vv.y, vv.y, ss);
        ss = fmaf(vv.z, vv.z, ss); ss = fmaf(vv.w, vv.w, ss);
    }
    __shared__ float red[20];
    for (int o = 16; o; o >>= 1) {
        s  += __shfl_down_sync(~0u, s, o);
        ss += __shfl_down_sync(~0u, ss, o);
    }
    if ((tid & 31) == 0) { red[tid >> 5] = s; red[8 + (tid >> 5)] = ss; }
    __syncthreads();
    if (tid == 0) {
        float S = 0.f, SS = 0.f;
        for (int i = 0; i < 8; i++) { S += red[i]; SS += red[8 + i]; }
        float mean = S * (1.f / 3072.f);
        float var  = SS * (1.f / 3072.f) - mean * mean;
        red[16] = mean;
        red[17] = rsqrtf(var + 1e-5f);
    }
    __syncthreads();
    float mean = red[16], rstd = red[17];

    float4 gr = ((const float4*)ln_g)[tid];
    float4 gc = ((const float4*)ln_g)[tid + 256];
    float4 gu = ((const float4*)ln_g)[tid + 512];
    float4 br4 = ((const float4*)ln_b)[tid];
    float4 bc4 = ((const float4*)ln_b)[tid + 256];
    float4 bu4 = ((const float4*)ln_b)[tid + 512];
    float4 dold = ((const float4*)(g_deter + (size_t)b * DETER))[tid];

    float* rr = &v[0].x; float* cc = &v[1].x; float* uu = &v[2].x;
    float* grp = &gr.x; float* gcp = &gc.x; float* gup = &gu.x;
    float* brp = &br4.x; float* bcp = &bc4.x; float* bup = &bu4.x;
    float* dop = &dold.x;

    float4 dnew;
    float* dnp = &dnew.x;
    unsigned short fvs[4];
#pragma unroll
    for (int j = 0; j < 4; j++) {
        float r = (rr[j] - mean) * rstd * grp[j] + brp[j];
        float c = (cc[j] - mean) * rstd * gcp[j] + bcp[j];
        float u = (uu[j] - mean) * rstd * gup[j] + bup[j];
        float reset  = sigm(r);
        float cand   = ftanh(reset * c);
        float update = sigm(u - 1.0f);
        float dn = update * cand + (1.f - update) * (m * dop[j]);
        dnp[j] = dn;
        h16 fv = __float2half(dn);
        fvs[j] = *(unsigned short*)&fv;
    }
    ((float4*)(g_deter + (size_t)b * DETER))[tid] = dnew;
    *(uint2*)&g_deterF[(size_t)b * DETER + 4 * tid] = *(uint2*)fvs;
    float* orow = out + ((size_t)b * T_ + t) * OUTDIM + 192;
    *(float4*)&orow[4 * tid] = dnew;
}

// ---------------- posterior dist (2 batches/CTA) + fused inp(t+1) -----------
__global__ void __launch_bounds__(256) k_post_inp(
                           const float* __restrict__ eps_post,
                           const float* __restrict__ bod,
                           float* __restrict__ out,
                           const float* __restrict__ action,
                           const unsigned char* __restrict__ is_first,
                           const float* __restrict__ W_inp,
                           const float* __restrict__ b_inp,
                           int t, int last) {
    const int b0 = blockIdx.x;           // handles b0 and b0+128
    const int tid = threadIdx.x;
    const int lane = tid & 31, wid = tid >> 5;

    __shared__ __align__(16) float sh[2048];   // [2][1024] xo
    __shared__ float sval[128];                // [2][64]
    __shared__ float spost[64];
    __shared__ float sin2[2][40];

    float4* sh4 = (float4*)sh;
#pragma unroll
    for (int ib = 0; ib < 2; ib++) {
        int b = b0 + ib * 128;
        const float4* xa = (const float4*)(g_xop0a + (size_t)b * 1024);
        const float4* xb = (const float4*)(g_xop0b + (size_t)b * 1024);
        const float4* xe = (const float4*)(g_xope + ((size_t)b * T_ + t) * 1024);
        float4 p = xa[tid], r = xb[tid], q = xe[tid];
        float4 f = { elu1(p.x + r.x + q.x), elu1(p.y + r.y + q.y),
                     elu1(p.z + r.z + q.z), elu1(p.w + r.w + q.w) };
        sh4[ib * 256 + tid] = f;
    }
    __syncthreads();

    for (int oo = wid; oo < 64; oo += 8) {
        const float4* w4 = (const float4*)(g_WodT + oo * 1024);
        const float4* a4 = (const float4*)sh;
        const float4* b4 = (const float4*)(sh + 1024);
        float s0 = 0.f, s1 = 0.f;
#pragma unroll
        for (int k = lane; k < 256; k += 32) {
            float4 w = w4[k], a = a4[k], b = b4[k];
            s0 += w.x * a.x + w.y * a.y + w.z * a.z + w.w * a.w;
            s1 += w.x * b.x + w.y * b.y + w.z * b.z + w.w * b.w;
        }
        for (int off = 16; off; off >>= 1) {
            s0 += __shfl_down_sync(~0u, s0, off);
            s1 += __shfl_down_sync(~0u, s1, off);
        }
        if (lane == 0) {
            float bb = bod[oo];
            sval[oo] = s0 + bb;
            sval[64 + oo] = s1 + bb;
        }
    }
    __syncthreads();

    if (tid < 64) {
        int ib = tid >> 5, j = tid & 31;
        int b = b0 + ib * 128;
        const float* sv = sval + ib * 64;
        float* orow = out + ((size_t)b * T_ + t) * OUTDIM;
        float om = sv[j];
        float os = splus(sv[32 + j]) + 0.1f;
        float eq = eps_post[((size_t)b * T_ + t) * STOCH + j];
        float post = fmaf(os, eq, om);
        orow[j]      = om;
        orow[32 + j] = os;
        orow[64 + j] = post;
        spost[ib * 32 + j] = post;
    }
    if (last) return;
    __syncthreads();

    // fused inp(t+1)
    if (tid < 38) {
        float m = is_first[b0 * T_ + t + 1] ? 0.f : 1.f;
        sin2[0][tid] = (tid < 32 ? spost[tid]
                        : action[((size_t)b0 * T_ + t + 1) * ACTD + tid - 32]) * m;
    } else if (tid < 76) {
        int j = tid - 38;
        int b1 = b0 + 128;
        float m = is_first[b1 * T_ + t + 1] ? 0.f : 1.f;
        sin2[1][j] = (j < 32 ? spost[32 + j]
                      : action[((size_t)b1 * T_ + t + 1) * ACTD + j - 32]) * m;
    }
    __syncthreads();
#pragma unroll
    for (int hh = 0; hh < 4; hh++) {
        int h = tid + hh * 256;
        float s0 = b_inp[h], s1 = s0;
#pragma unroll
        for (int k = 0; k < STOCH + ACTD; k++) {
            float w = W_inp[k * HIDDEN + h];
            s0 = fmaf(sin2[0][k], w, s0);
            s1 = fmaf(sin2[1][k], w, s1);
        }
        g_xF[b0 * HIDDEN + h] = __float2half(elu1(s0));
        g_xF[(b0 + 128) * HIDDEN + h] = __float2half(elu1(s1));
    }
}

// ---------------- prior dist (2 batches/CTA), background stream -------------
__global__ void __launch_bounds__(256) k_prior(
                        const float* __restrict__ eps_prior,
                        const int* __restrict__ ens_idx,
                        const float* __restrict__ bed,
                        float* __restrict__ out, int t) {
    const int b0 = blockIdx.x;
    const int tid = threadIdx.x;
    const int lane = tid & 31, wid = tid >> 5;
    const int idx = __ldg(&ens_idx[t]);

    __shared__ __align__(16) float sh[2048];   // [2][1024] h
    __shared__ float sval[128];

    float4* sh4 = (float4*)sh;
#pragma unroll
    for (int ib = 0; ib < 2; ib++) {
        int b = b0 + ib * 128;
        const float4* h0 = (const float4*)(g_hp0 + (size_t)b * 1024);
        const float4* h1 = (const float4*)(g_hp1 + (size_t)b * 1024);
        float4 a = h0[tid], c = h1[tid];
        float4 e = { elu1(a.x + c.x), elu1(a.y + c.y),
                     elu1(a.z + c.z), elu1(a.w + c.w) };
        sh4[ib * 256 + tid] = e;
    }
    __syncthreads();

    for (int oo = wid; oo < 64; oo += 8) {
        const float4* w4 = (const float4*)(g_WedT + (size_t)idx * 65536 + oo * 1024);
        const float4* a4 = (const float4*)sh;
        const float4* b4 = (const float4*)(sh + 1024);
        float s0 = 0.f, s1 = 0.f;
#pragma unroll
        for (int k = lane; k < 256; k += 32) {
            float4 w = w4[k], a = a4[k], b = b4[k];
            s0 += w.x * a.x + w.y * a.y + w.z * a.z + w.w * a.w;
            s1 += w.x * b.x + w.y * b.y + w.z * b.z + w.w * b.w;
        }
        for (int off = 16; off; off >>= 1) {
            s0 += __shfl_down_sync(~0u, s0, off);
            s1 += __shfl_down_sync(~0u, s1, off);
        }
        if (lane == 0) {
            float bb = bed[idx * 64 + oo];
            sval[oo] = s0 + bb;
            sval[64 + oo] = s1 + bb;
        }
    }
    __syncthreads();

    if (tid < 64) {
        int ib = tid >> 5, j = tid & 31;
        int b = b0 + ib * 128;
        const float* sv = sval + ib * 64;
        float* orow = out + ((size_t)b * T_ + t) * OUTDIM;
        float pm = sv[j];
        float ps = splus(sv[32 + j]) + 0.1f;
        float ep = eps_prior[((size_t)b * T_ + t) * STOCH + j];
        float prior = fmaf(ps, ep, pm);
        orow[96 + j]  = pm;
        orow[128 + j] = ps;
        orow[160 + j] = prior;
    }
}

// ---------------- launch ----------------------------------------------------
extern "C" void kernel_launch(void* const* d_in, const int* in_sizes, int n_in,
                              void* d_out, int out_size) {
    const float* embed      = (const float*)d_in[0];
    const float* action     = (const float*)d_in[1];
    const float* eps_post   = (const float*)d_in[2];
    const float* eps_prior  = (const float*)d_in[3];
    const unsigned char* is_first = (const unsigned char*)d_in[4];
    const int*   ens_idx    = (const int*)d_in[5];
    const float* W_gru      = (const float*)d_in[6];
    const float* b_gru      = (const float*)d_in[7];
    const float* ln_g       = (const float*)d_in[8];
    const float* ln_b       = (const float*)d_in[9];
    const float* W_inp      = (const float*)d_in[10];
    const float* b_inp      = (const float*)d_in[11];
    const float* W_obs      = (const float*)d_in[12];
    const float* b_obs      = (const float*)d_in[13];
    const float* W_ens      = (const float*)d_in[14];
    const float* b_ens      = (const float*)d_in[15];
    const float* W_obs_dist = (const float*)d_in[16];
    const float* b_obs_dist = (const float*)d_in[17];
    const float* W_ens_dist = (const float*)d_in[18];
    const float* b_ens_dist = (const float*)d_in[19];
    float* out = (float*)d_out;

    h16 *wgH, *wgL, *woH, *woL, *weH, *weL, *emF, *xF, *dF;
    float *ppa, *ppb, *pp1, *php0, *php1, *pxa, *pxb, *pxope;
    cudaGetSymbolAddress((void**)&wgH, g_WgruH);
    cudaGetSymbolAddress((void**)&wgL, g_WgruL);
    cudaGetSymbolAddress((void**)&woH, g_WobsH);
    cudaGetSymbolAddress((void**)&woL, g_WobsL);
    cudaGetSymbolAddress((void**)&weH, g_WensH);
    cudaGetSymbolAddress((void**)&weL, g_WensL);
    cudaGetSymbolAddress((void**)&emF, g_embF);
    cudaGetSymbolAddress((void**)&xF,  g_xF);
    cudaGetSymbolAddress((void**)&dF,  g_deterF);
    cudaGetSymbolAddress((void**)&ppa, g_pp0a);
    cudaGetSymbolAddress((void**)&ppb, g_pp0b);
    cudaGetSymbolAddress((void**)&pp1, g_pp1);
    cudaGetSymbolAddress((void**)&php0, g_hp0);
    cudaGetSymbolAddress((void**)&php1, g_hp1);
    cudaGetSymbolAddress((void**)&pxa, g_xop0a);
    cudaGetSymbolAddress((void**)&pxb, g_xop0b);
    cudaGetSymbolAddress((void**)&pxope, g_xope);

    // persistent streams/events (host objects, created once)
    static cudaStream_t s2 = 0, s3 = 0;
    static cudaEvent_t e0 = 0, eW = 0, eEmb = 0, eTr = 0, eGate = 0,
                       eBg = 0, eFin = 0;
    if (!s2) {
        int lo = 0, hi = 0;
        cudaDeviceGetStreamPriorityRange(&lo, &hi);
        cudaStreamCreateWithPriority(&s2, cudaStreamNonBlocking, lo);
        cudaStreamCreateWithPriority(&s3, cudaStreamNonBlocking, lo);
        cudaEventCreateWithFlags(&e0,    cudaEventDisableTiming);
        cudaEventCreateWithFlags(&eW,    cudaEventDisableTiming);
        cudaEventCreateWithFlags(&eEmb,  cudaEventDisableTiming);
        cudaEventCreateWithFlags(&eTr,   cudaEventDisableTiming);
        cudaEventCreateWithFlags(&eGate, cudaEventDisableTiming);
        cudaEventCreateWithFlags(&eBg,   cudaEventDisableTiming);
        cudaEventCreateWithFlags(&eFin,  cudaEventDisableTiming);
    }

    // common subs
    SubTC subGruXa = { xF, HIDDEN, wgH, wgL, 3072, 512, 0,
                       b_gru, ppa, 3072, 0, 0, 4 };
    SubTC subGruXb = { xF + 512, HIDDEN,
                       wgH + (size_t)512 * 3072, wgL + (size_t)512 * 3072,
                       3072, 512, 0, nullptr, ppb, 3072, 0, 0, 4 };
    SubTC subGruD  = { dF, DETER, wgH + (size_t)1024 * 3072,
                       wgL + (size_t)1024 * 3072, 3072, 1024, 0,
                       nullptr, pp1, 3072, 0, 0, 4 };
    SubTC subEns0 = { dF, DETER, weH, weL, 1024, 512, 1,
                      b_ens, php0, 1024, (long long)DETER * HIDDEN, HIDDEN, 4 };
    SubTC subEns1 = { dF + 512, DETER,
                      weH + (size_t)512 * 1024, weL + (size_t)512 * 1024,
                      1024, 512, 1,
                      nullptr, php1, 1024, (long long)DETER * HIDDEN, HIDDEN, 4 };
    SubTC subObsDa = { dF, DETER, woH, woL, 1024, 512, 0,
                       b_obs, pxa, 1024, 0, 0, 4 };
    SubTC subObsDb = { dF + 512, DETER,
                       woH + (size_t)512 * 1024, woL + (size_t)512 * 1024,
                       1024, 512, 0, nullptr, pxb, 1024, 0, 0, 4 };

    // ---- setup: stream 0 ----
    k_init<<<(B_ * DETER + 255) / 256, 256>>>();
    cudaEventRecord(e0, 0);
    k_split<<<4096, 256>>>(W_obs, woH, woL, 2560 * 1024);
    cudaEventRecord(eW, 0);
    k_split<<<4096, 256>>>(W_gru, wgH, wgL, 2048 * 3072);
    k_transpose<<<(6 * 65536) / 256, 256>>>(W_obs_dist, W_ens_dist);
    cudaEventRecord(eTr, 0);
    k_inp0<<<B_, 256>>>(action, is_first, W_inp, b_inp);

    // prologue: full GRU GEMM for t=0
    {
        ParamsTC p = {};
        p.s[0] = subGruXa;
        p.s[1] = subGruXb;
        p.s[2] = subGruD;
        p.start[0] = 0; p.start[1] = 192; p.start[2] = 384; p.start[3] = 576;
        p.nsub = 3;
        gemm_tc<<<576, 128>>>(p, ens_idx, 0);
    }

    // ---- s2: embed cast + xope GEMM (setup only) ----
    cudaStreamWaitEvent(s2, e0, 0);
    k_cast<<<8192, 256, 0, s2>>>(embed, emF, B_ * T_ * EMBED);
    cudaStreamWaitEvent(s2, eW, 0);
    {
        ParamsTC p = {};
        p.s[0] = { emF, EMBED,
                   woH + (size_t)1024 * 1024, woL + (size_t)1024 * 1024, 1024,
                   1536, 0, nullptr, pxope, 1024, 0, 0, 256 };
        p.start[0] = 0; p.start[1] = 4096;
        p.nsub = 1;
        gemm_tc<<<4096, 128, 0, s2>>>(p, ens_idx, 0);
    }
    cudaEventRecord(eEmb, s2);

    // ---- s3: Wens split + per-step background ----
    cudaStreamWaitEvent(s3, e0, 0);
    k_split<<<4096, 256, 0, s3>>>(W_ens, weH, weL, ENS * 1024 * 1024);
    cudaStreamWaitEvent(s3, eTr, 0);   // prior needs WedT

    // xope ready before the loop
    cudaStreamWaitEvent(0, eEmb, 0);

    for (int t = 0; t < T_; t++) {
        // gate(t) — needs pp0a/pp0b (main) and pp1 (bg, joined via eBg)
        k_gate<<<B_, 256>>>(ln_g, ln_b, is_first, out, t);
        cudaEventRecord(eGate, 0);

        // background (s3): ens(t) [+ gruD(t+1)] GEMM, then prior dist(t)
        cudaStreamWaitEvent(s3, eGate, 0);
        {
            ParamsTC p = {};
            p.s[0] = subEns0;
            p.s[1] = subEns1;
            p.start[0] = 0; p.start[1] = 64; p.start[2] = 128;
            p.nsub = 2;
            int grid = 128;
            if (t + 1 < T_) {
                p.s[2] = subGruD;
                p.start[3] = 320;
                p.nsub = 3;
                grid = 320;
            }
            gemm_tc<<<grid, 128, 0, s3>>>(p, ens_idx, t);
        }
        cudaEventRecord(eBg, s3);
        k_prior<<<B_ / 2, 256, 0, s3>>>(eps_prior, ens_idx, b_ens_dist, out, t);

        // critical: obs-deter GEMM, split-K (128 tiles)
        {
            ParamsTC p = {};
            p.s[0] = subObsDa;
            p.s[1] = subObsDb;
            p.start[0] = 0; p.start[1] = 64; p.start[2] = 128;
            p.nsub = 2;
            gemm_tc<<<128, 128>>>(p, ens_idx, t);
        }

        // posterior + fused inp(t+1)
        k_post_inp<<<B_ / 2, 256>>>(eps_post, b_obs_dist, out,
                                    action, is_first, W_inp, b_inp,
                                    t, t + 1 == T_);

        if (t + 1 < T_) {
            ParamsTC p = {};
            p.s[0] = subGruXa;
            p.s[1] = subGruXb;
            p.start[0] = 0; p.start[1] = 192; p.start[2] = 384;
            p.nsub = 2;
            gemm_tc<<<384, 128>>>(p, ens_idx, t + 1);
            cudaStreamWaitEvent(0, eBg, 0);   // pp1 ready before gate(t+1)
        }
    }

    // final join: all background work before harness reads
    cudaEventRecord(eFin, s3);
    cudaStreamWaitEvent(0, eFin, 0);
}

// round 17
// speedup vs baseline: 1.5976x; 1.4115x over previous
#include <cuda_runtime.h>
#include <cuda_fp16.h>
#include <math.h>
#include <stddef.h>

typedef __half h16;

#define B_      256
#define T_      64
#define STOCH   32
#define DETER   1024
#define HIDDEN  1024
#define EMBED   1536
#define ACTD    6
#define ENS     5
#define OUTDIM  1216   // 6*STOCH + DETER

// ---------------- scratch (device globals; no allocation allowed) ----------
__device__ __align__(16) h16 g_WgruH[2048 * 3072];
__device__ __align__(16) h16 g_WgruL[2048 * 3072];
__device__ __align__(16) h16 g_WobsH[2560 * 1024];
__device__ __align__(16) h16 g_WobsL[2560 * 1024];
__device__ __align__(16) h16 g_WensH[ENS * 1024 * 1024];
__device__ __align__(16) h16 g_WensL[ENS * 1024 * 1024];
__device__ __align__(16) h16 g_embF[B_ * T_ * EMBED];
__device__ __align__(16) h16 g_xF[B_ * HIDDEN];
__device__ __align__(16) h16 g_deterF[B_ * DETER];

__device__ __align__(16) float g_pp0[4][B_ * 3072];    // gruX K-chunk partials
__device__ __align__(16) float g_pp1[B_ * 3072];
__device__ __align__(16) float g_hp0[B_ * 1024];
__device__ __align__(16) float g_hp1[B_ * 1024];
__device__ __align__(16) float g_xop[4][B_ * 1024];    // obsD K-chunk partials
__device__ __align__(16) float g_xope[B_ * T_ * 1024]; // embed@Wobs, all t
__device__ __align__(16) float g_stoch[B_ * STOCH];
__device__ __align__(16) float g_deter[B_ * DETER];
__device__ __align__(16) float g_WodT[64 * 1024];
__device__ __align__(16) float g_WedT[ENS * 64 * 1024];

// ---------------- fast-math helpers (MUFU; err ~1e-7 rel) -------------------
#define LOG2E 1.4426950408889634f
#define LN2   0.6931471805599453f
__device__ __forceinline__ float fex2(float x) {
    float r; asm("ex2.approx.f32 %0, %1;" : "=f"(r) : "f"(x)); return r;
}
__device__ __forceinline__ float flg2(float x) {
    float r; asm("lg2.approx.f32 %0, %1;" : "=f"(r) : "f"(x)); return r;
}
__device__ __forceinline__ float frcpa(float x) {
    float r; asm("rcp.approx.f32 %0, %1;" : "=f"(r) : "f"(x)); return r;
}
__device__ __forceinline__ float elu1(float x) {
    return x > 0.f ? x : fex2(LOG2E * x) - 1.f;
}
__device__ __forceinline__ float sigm(float x) {
    return frcpa(1.f + fex2(-LOG2E * x));
}
__device__ __forceinline__ float ftanh(float x) {
    float e = fex2(2.f * LOG2E * x);
    return 1.f - 2.f * frcpa(e + 1.f);
}
__device__ __forceinline__ float splus(float x) {
    return fmaxf(x, 0.f) + LN2 * flg2(1.f + fex2(-LOG2E * fabsf(x)));
}

// ---------------- setup kernels ---------------------------------------------
__global__ void k_init() {
    int i = blockIdx.x * blockDim.x + threadIdx.x;
    if (i < B_ * STOCH) g_stoch[i] = 0.f;
    if (i < B_ * DETER) {
        g_deter[i] = 0.f;
        g_deterF[i] = __float2half(0.f);
    }
}

// weights: float -> fp16 hi + fp16 lo(residual)
__global__ void k_split(const float* __restrict__ src, h16* __restrict__ hi,
                        h16* __restrict__ lo, int n) {
    for (int i = blockIdx.x * blockDim.x + threadIdx.x; i < n;
         i += gridDim.x * blockDim.x) {
        float v = src[i];
        h16 h = __float2half(v);
        hi[i] = h;
        lo[i] = __float2half(v - __half2float(h));
    }
}

// activations: float -> single fp16
__global__ void k_cast(const float* __restrict__ src, h16* __restrict__ dst,
                       int n) {
    for (int i = blockIdx.x * blockDim.x + threadIdx.x; i < n;
         i += gridDim.x * blockDim.x)
        dst[i] = __float2half(src[i]);
}

__global__ void k_transpose(const float* __restrict__ Wod,
                            const float* __restrict__ Wed) {
    int i = blockIdx.x * blockDim.x + threadIdx.x;  // 6*65536
    int part = i >> 16;
    int r = i & 65535;
    int j = r >> 10;
    int k = r & 1023;
    if (part == 0) {
        g_WodT[r] = Wod[k * 64 + j];
    } else {
        int h = part - 1;
        g_WedT[(size_t)h * 65536 + r] = Wed[(size_t)h * 65536 + k * 64 + j];
    }
}

// ---------------- prologue: inp for t=0 --------------------------------------
__global__ void k_inp0(const float* __restrict__ action,
                       const unsigned char* __restrict__ is_first,
                       const float* __restrict__ W_inp,
                       const float* __restrict__ b_inp) {
    int b = blockIdx.x;
    int tid = threadIdx.x;
    __shared__ float in[STOCH + ACTD];
    float m = is_first[b * T_] ? 0.f : 1.f;
    if (tid < STOCH)
        in[tid] = 0.f;
    else if (tid < STOCH + ACTD)
        in[tid] = action[(size_t)b * T_ * ACTD + (tid - STOCH)] * m;
    __syncthreads();
    for (int h = tid; h < HIDDEN; h += 256) {
        float s = b_inp[h];
#pragma unroll
        for (int k = 0; k < STOCH + ACTD; k++)
            s = fmaf(in[k], W_inp[k * HIDDEN + h], s);
        g_xF[b * HIDDEN + h] = __float2half(elu1(s));
    }
}

// ---------------- tensor-core fp16 2-term GEMM, flat multi-sub ---------------
struct SubTC {
    const h16* aF; long long lda;
    const h16* wH; const h16* wL; long long ldw;
    int K; int ens;
    const float* bias;
    float* C; long long ldc;
    long long wstride, bstride;
    int mt;                      // M tiles (row tiles) for this sub
};
struct ParamsTC { SubTC s[4]; int start[5]; int nsub; };

__device__ __forceinline__ unsigned saddr(const void* p) {
    return (unsigned)__cvta_generic_to_shared(p);
}
__device__ __forceinline__ void ldsm4(unsigned a, unsigned* r) {
    asm volatile("ldmatrix.sync.aligned.m8n8.x4.shared.b16 {%0,%1,%2,%3}, [%4];"
                 : "=r"(r[0]), "=r"(r[1]), "=r"(r[2]), "=r"(r[3]) : "r"(a));
}
__device__ __forceinline__ void ldsm4t(unsigned a, unsigned* r) {
    asm volatile("ldmatrix.sync.aligned.m8n8.x4.trans.shared.b16 {%0,%1,%2,%3}, [%4];"
                 : "=r"(r[0]), "=r"(r[1]), "=r"(r[2]), "=r"(r[3]) : "r"(a));
}
__device__ __forceinline__ void mma16816(float* c, const unsigned* a,
                                         unsigned b0, unsigned b1) {
    asm volatile(
        "mma.sync.aligned.m16n8k16.row.col.f32.f16.f16.f32 "
        "{%0,%1,%2,%3},{%4,%5,%6,%7},{%8,%9},{%0,%1,%2,%3};"
        : "+f"(c[0]), "+f"(c[1]), "+f"(c[2]), "+f"(c[3])
        : "r"(a[0]), "r"(a[1]), "r"(a[2]), "r"(a[3]), "r"(b0), "r"(b1));
}

__global__ void __launch_bounds__(128) gemm_tc(ParamsTC p,
                                               const int* __restrict__ ens_idx,
                                               int t) {
    const int w = blockIdx.x;
    int si = 0;
#pragma unroll
    for (int i = 1; i < 4; i++)
        if (i < p.nsub && w >= p.start[i]) si = i;
    SubTC s = p.s[si];
    const int r = w - p.start[si];
    const int bm = (r % s.mt) << 6, bn = (r / s.mt) << 6;

    const h16* wH = s.wH;
    const h16* wL = s.wL;
    const float* bias = s.bias;
    if (s.ens) {
        int idx = __ldg(&ens_idx[t]);
        wH += (long long)idx * s.wstride;
        wL += (long long)idx * s.wstride;
        if (bias) bias += (long long)idx * s.bstride;
    }
    const int tid = threadIdx.x, lane = tid & 31, warp = tid >> 5;
    const int warpM = warp & 1, warpN = warp >> 1;

    __shared__ __align__(16) h16 AsF[2][64][32];
    __shared__ __align__(16) h16 BsH[2][32][64], BsL[2][32][64];

    const int ar = tid >> 2, ac = tid & 3;
    const int apc = (ac ^ ((ar >> 1) & 3)) * 8;
    const int br = tid >> 3, bc = tid & 7;
    const int bpc = (bc ^ (br & 7)) * 8;

    const h16* aFp = s.aF + (long long)(bm + ar) * s.lda + ac * 8;
    const h16* wHp = wH + (long long)br * s.ldw + bn + bc * 8;
    const h16* wLp = wL + (long long)br * s.ldw + bn + bc * 8;
    const long long aRowStep = 32 * s.lda;
    const long long bRowStep = 16 * s.ldw;
    const long long bKStep = 32 * s.ldw;

    uint4 pAF0, pAF1, pBH0, pBH1, pBL0, pBL1;
    auto loadStage = [&](int kt) {
        const h16* a = aFp + kt * 32;
        pAF0 = *(const uint4*)a;
        pAF1 = *(const uint4*)(a + aRowStep);
        const h16* b = wHp + (long long)kt * bKStep;
        pBH0 = *(const uint4*)b;
        pBH1 = *(const uint4*)(b + bRowStep);
        const h16* bl = wLp + (long long)kt * bKStep;
        pBL0 = *(const uint4*)bl;
        pBL1 = *(const uint4*)(bl + bRowStep);
    };
    auto storeStage = [&](int bb) {
        *(uint4*)&AsF[bb][ar][apc] = pAF0;
        *(uint4*)&AsF[bb][ar + 32][apc] = pAF1;
        *(uint4*)&BsH[bb][br][bpc] = pBH0;
        *(uint4*)&BsH[bb][br + 16][bpc] = pBH1;
        *(uint4*)&BsL[bb][br][bpc] = pBL0;
        *(uint4*)&BsL[bb][br + 16][bpc] = pBL1;
    };

    float acc[2][4][4] = {};
    const int lrow = lane & 15, lsel = lane >> 4;

    loadStage(0);
    storeStage(0);
    __syncthreads();

    const int nt = s.K >> 5;
    int buf = 0;
    for (int kt = 0; kt < nt; kt++) {
        if (kt + 1 < nt) loadStage(kt + 1);
#pragma unroll
        for (int ks = 0; ks < 2; ks++) {
            unsigned aFf[2][4], bHf[2][4], bLf[2][4];
#pragma unroll
            for (int tm = 0; tm < 2; tm++) {
                int rr = warpM * 32 + tm * 16 + lrow;
                int pc = ((ks * 2 + lsel) ^ ((rr >> 1) & 3)) * 8;
                ldsm4(saddr(&AsF[buf][rr][pc]), aFf[tm]);
            }
            int kr = ks * 16 + lrow;
#pragma unroll
            for (int tn = 0; tn < 2; tn++) {
                int pc = ((warpN * 4 + tn * 2 + lsel) ^ (kr & 7)) * 8;
                ldsm4t(saddr(&BsH[buf][kr][pc]), bHf[tn]);
                ldsm4t(saddr(&BsL[buf][kr][pc]), bLf[tn]);
            }
#pragma unroll
            for (int tm = 0; tm < 2; tm++)
#pragma unroll
                for (int j = 0; j < 4; j++) {
                    unsigned bh0 = bHf[j >> 1][(j & 1) * 2];
                    unsigned bh1 = bHf[j >> 1][(j & 1) * 2 + 1];
                    unsigned bl0 = bLf[j >> 1][(j & 1) * 2];
                    unsigned bl1 = bLf[j >> 1][(j & 1) * 2 + 1];
                    mma16816(acc[tm][j], aFf[tm], bh0, bh1);
                    mma16816(acc[tm][j], aFf[tm], bl0, bl1);
                }
        }
        if (kt + 1 < nt) storeStage(buf ^ 1);
        __syncthreads();
        buf ^= 1;
    }

    const int g = lane >> 2, tg = lane & 3;
#pragma unroll
    for (int tm = 0; tm < 2; tm++) {
        int row = bm + warpM * 32 + tm * 16 + g;
#pragma unroll
        for (int j = 0; j < 4; j++) {
            int col = bn + warpN * 32 + j * 8 + tg * 2;
            float bx = bias ? bias[col] : 0.f;
            float by = bias ? bias[col + 1] : 0.f;
            float2 v0 = { acc[tm][j][0] + bx, acc[tm][j][1] + by };
            float2 v1 = { acc[tm][j][2] + bx, acc[tm][j][3] + by };
            *(float2*)&s.C[(long long)row * s.ldc + col] = v0;
            *(float2*)&s.C[(long long)(row + 8) * s.ldc + col] = v1;
        }
    }
}

// ---------------- gate: masked sum + LayerNorm + GRU update -----------------
__global__ void __launch_bounds__(256) k_gate(const float* __restrict__ ln_g,
                       const float* __restrict__ ln_b,
                       const unsigned char* __restrict__ is_first,
                       float* __restrict__ out, int t) {
    int b = blockIdx.x, tid = threadIdx.x;
    float m = is_first[b * T_ + t] ? 0.f : 1.f;
    const float4* p14 = (const float4*)(g_pp1 + (size_t)b * 3072);

    float4 v[3];
    float s = 0.f, ss = 0.f;
#pragma unroll
    for (int i = 0; i < 3; i++) {
        int ix = tid + i * 256;
        int gi = b * 768 + ix;
        float4 a0 = ((const float4*)g_pp0[0])[gi];
        float4 a1 = ((const float4*)g_pp0[1])[gi];
        float4 a2 = ((const float4*)g_pp0[2])[gi];
        float4 a3 = ((const float4*)g_pp0[3])[gi];
        float4 c = p14[ix];
        float4 vv;
        vv.x = fmaf(m, c.x, (a0.x + a1.x) + (a2.x + a3.x));
        vv.y = fmaf(m, c.y, (a0.y + a1.y) + (a2.y + a3.y));
        vv.z = fmaf(m, c.z, (a0.z + a1.z) + (a2.z + a3.z));
        vv.w = fmaf(m, c.w, (a0.w + a1.w) + (a2.w + a3.w));
        v[i] = vv;
        s += vv.x + vv.y + vv.z + vv.w;
        ss = fmaf(vv.x, vv.x, ss); ss = fmaf(vv.y, vv.y, ss);
        ss = fmaf(vv.z, vv.z, ss); ss = fmaf(vv.w, vv.w, ss);
    }
    __shared__ float red[20];
    for (int o = 16; o; o >>= 1) {
        s  += __shfl_down_sync(~0u, s, o);
        ss += __shfl_down_sync(~0u, ss, o);
    }
    if ((tid & 31) == 0) { red[tid >> 5] = s; red[8 + (tid >> 5)] = ss; }
    __syncthreads();
    if (tid == 0) {
        float S = 0.f, SS = 0.f;
        for (int i = 0; i < 8; i++) { S += red[i]; SS += red[8 + i]; }
        float mean = S * (1.f / 3072.f);
        float var  = SS * (1.f / 3072.f) - mean * mean;
        red[16] = mean;
        red[17] = rsqrtf(var + 1e-5f);
    }
    __syncthreads();
    float mean = red[16], rstd = red[17];

    float4 gr = ((const float4*)ln_g)[tid];
    float4 gc = ((const float4*)ln_g)[tid + 256];
    float4 gu = ((const float4*)ln_g)[tid + 512];
    float4 br4 = ((const float4*)ln_b)[tid];
    float4 bc4 = ((const float4*)ln_b)[tid + 256];
    float4 bu4 = ((const float4*)ln_b)[tid + 512];
    float4 dold = ((const float4*)(g_deter + (size_t)b * DETER))[tid];

    float* rr = &v[0].x; float* cc = &v[1].x; float* uu = &v[2].x;
    float* grp = &gr.x; float* gcp = &gc.x; float* gup = &gu.x;
    float* brp = &br4.x; float* bcp = &bc4.x; float* bup = &bu4.x;
    float* dop = &dold.x;

    float4 dnew;
    float* dnp = &dnew.x;
    unsigned short fvs[4];
#pragma unroll
    for (int j = 0; j < 4; j++) {
        float r = (rr[j] - mean) * rstd * grp[j] + brp[j];
        float c = (cc[j] - mean) * rstd * gcp[j] + bcp[j];
        float u = (uu[j] - mean) * rstd * gup[j] + bup[j];
        float reset  = sigm(r);
        float cand   = ftanh(reset * c);
        float update = sigm(u - 1.0f);
        float dn = update * cand + (1.f - update) * (m * dop[j]);
        dnp[j] = dn;
        h16 fv = __float2half(dn);
        fvs[j] = *(unsigned short*)&fv;
    }
    ((float4*)(g_deter + (size_t)b * DETER))[tid] = dnew;
    *(uint2*)&g_deterF[(size_t)b * DETER + 4 * tid] = *(uint2*)fvs;
    float* orow = out + ((size_t)b * T_ + t) * OUTDIM + 192;
    *(float4*)&orow[4 * tid] = dnew;
}

// ---------------- posterior dist (2 batches/CTA) + fused inp(t+1) -----------
__global__ void __launch_bounds__(256) k_post_inp(
                           const float* __restrict__ eps_post,
                           const float* __restrict__ bod,
                           float* __restrict__ out,
                           const float* __restrict__ action,
                           const unsigned char* __restrict__ is_first,
                           const float* __restrict__ W_inp,
                           const float* __restrict__ b_inp,
                           int t, int last) {
    const int b0 = blockIdx.x;           // handles b0 and b0+128
    const int tid = threadIdx.x;
    const int lane = tid & 31, wid = tid >> 5;

    __shared__ __align__(16) float sh[2048];   // [2][1024] xo
    __shared__ float sval[128];                // [2][64]
    __shared__ float spost[64];
    __shared__ float sin2[2][40];

    float4* sh4 = (float4*)sh;
#pragma unroll
    for (int ib = 0; ib < 2; ib++) {
        int b = b0 + ib * 128;
        int gi = b * 256 + tid;
        float4 x0 = ((const float4*)g_xop[0])[gi];
        float4 x1 = ((const float4*)g_xop[1])[gi];
        float4 x2 = ((const float4*)g_xop[2])[gi];
        float4 x3 = ((const float4*)g_xop[3])[gi];
        float4 xe = ((const float4*)g_xope)[((size_t)b * T_ + t) * 256 + tid];
        float4 f = { elu1((x0.x + x1.x) + (x2.x + x3.x) + xe.x),
                     elu1((x0.y + x1.y) + (x2.y + x3.y) + xe.y),
                     elu1((x0.z + x1.z) + (x2.z + x3.z) + xe.z),
                     elu1((x0.w + x1.w) + (x2.w + x3.w) + xe.w) };
        sh4[ib * 256 + tid] = f;
    }
    __syncthreads();

    for (int oo = wid; oo < 64; oo += 8) {
        const float4* w4 = (const float4*)(g_WodT + oo * 1024);
        const float4* a4 = (const float4*)sh;
        const float4* b4 = (const float4*)(sh + 1024);
        float s0 = 0.f, s1 = 0.f;
#pragma unroll
        for (int k = lane; k < 256; k += 32) {
            float4 w = w4[k], a = a4[k], b = b4[k];
            s0 += w.x * a.x + w.y * a.y + w.z * a.z + w.w * a.w;
            s1 += w.x * b.x + w.y * b.y + w.z * b.z + w.w * b.w;
        }
        for (int off = 16; off; off >>= 1) {
            s0 += __shfl_down_sync(~0u, s0, off);
            s1 += __shfl_down_sync(~0u, s1, off);
        }
        if (lane == 0) {
            float bb = bod[oo];
            sval[oo] = s0 + bb;
            sval[64 + oo] = s1 + bb;
        }
    }
    __syncthreads();

    if (tid < 64) {
        int ib = tid >> 5, j = tid & 31;
        int b = b0 + ib * 128;
        const float* sv = sval + ib * 64;
        float* orow = out + ((size_t)b * T_ + t) * OUTDIM;
        float om = sv[j];
        float os = splus(sv[32 + j]) + 0.1f;
        float eq = eps_post[((size_t)b * T_ + t) * STOCH + j];
        float post = fmaf(os, eq, om);
        orow[j]      = om;
        orow[32 + j] = os;
        orow[64 + j] = post;
        spost[ib * 32 + j] = post;
    }
    if (last) return;
    __syncthreads();

    // fused inp(t+1)
    if (tid < 38) {
        float m = is_first[b0 * T_ + t + 1] ? 0.f : 1.f;
        sin2[0][tid] = (tid < 32 ? spost[tid]
                        : action[((size_t)b0 * T_ + t + 1) * ACTD + tid - 32]) * m;
    } else if (tid < 76) {
        int j = tid - 38;
        int b1 = b0 + 128;
        float m = is_first[b1 * T_ + t + 1] ? 0.f : 1.f;
        sin2[1][j] = (j < 32 ? spost[32 + j]
                      : action[((size_t)b1 * T_ + t + 1) * ACTD + j - 32]) * m;
    }
    __syncthreads();
#pragma unroll
    for (int hh = 0; hh < 4; hh++) {
        int h = tid + hh * 256;
        float s0 = b_inp[h], s1 = s0;
#pragma unroll
        for (int k = 0; k < STOCH + ACTD; k++) {
            float w = W_inp[k * HIDDEN + h];
            s0 = fmaf(sin2[0][k], w, s0);
            s1 = fmaf(sin2[1][k], w, s1);
        }
        g_xF[b0 * HIDDEN + h] = __float2half(elu1(s0));
        g_xF[(b0 + 128) * HIDDEN + h] = __float2half(elu1(s1));
    }
}

// ---------------- prior dist (2 batches/CTA), background stream -------------
__global__ void __launch_bounds__(256) k_prior(
                        const float* __restrict__ eps_prior,
                        const int* __restrict__ ens_idx,
                        const float* __restrict__ bed,
                        float* __restrict__ out, int t) {
    const int b0 = blockIdx.x;
    const int tid = threadIdx.x;
    const int lane = tid & 31, wid = tid >> 5;
    const int idx = __ldg(&ens_idx[t]);

    __shared__ __align__(16) float sh[2048];   // [2][1024] h
    __shared__ float sval[128];

    float4* sh4 = (float4*)sh;
#pragma unroll
    for (int ib = 0; ib < 2; ib++) {
        int b = b0 + ib * 128;
        const float4* h0 = (const float4*)(g_hp0 + (size_t)b * 1024);
        const float4* h1 = (const float4*)(g_hp1 + (size_t)b * 1024);
        float4 a = h0[tid], c = h1[tid];
        float4 e = { elu1(a.x + c.x), elu1(a.y + c.y),
                     elu1(a.z + c.z), elu1(a.w + c.w) };
        sh4[ib * 256 + tid] = e;
    }
    __syncthreads();

    for (int oo = wid; oo < 64; oo += 8) {
        const float4* w4 = (const float4*)(g_WedT + (size_t)idx * 65536 + oo * 1024);
        const float4* a4 = (const float4*)sh;
        const float4* b4 = (const float4*)(sh + 1024);
        float s0 = 0.f, s1 = 0.f;
#pragma unroll
        for (int k = lane; k < 256; k += 32) {
            float4 w = w4[k], a = a4[k], b = b4[k];
            s0 += w.x * a.x + w.y * a.y + w.z * a.z + w.w * a.w;
            s1 += w.x * b.x + w.y * b.y + w.z * b.z + w.w * b.w;
        }
        for (int off = 16; off; off >>= 1) {
            s0 += __shfl_down_sync(~0u, s0, off);
            s1 += __shfl_down_sync(~0u, s1, off);
        }
        if (lane == 0) {
            float bb = bed[idx * 64 + oo];
            sval[oo] = s0 + bb;
            sval[64 + oo] = s1 + bb;
        }
    }
    __syncthreads();

    if (tid < 64) {
        int ib = tid >> 5, j = tid & 31;
        int b = b0 + ib * 128;
        const float* sv = sval + ib * 64;
        float* orow = out + ((size_t)b * T_ + t) * OUTDIM;
        float pm = sv[j];
        float ps = splus(sv[32 + j]) + 0.1f;
        float ep = eps_prior[((size_t)b * T_ + t) * STOCH + j];
        float prior = fmaf(ps, ep, pm);
        orow[96 + j]  = pm;
        orow[128 + j] = ps;
        orow[160 + j] = prior;
    }
}

// ---------------- launch ----------------------------------------------------
extern "C" void kernel_launch(void* const* d_in, const int* in_sizes, int n_in,
                              void* d_out, int out_size) {
    const float* embed      = (const float*)d_in[0];
    const float* action     = (const float*)d_in[1];
    const float* eps_post   = (const float*)d_in[2];
    const float* eps_prior  = (const float*)d_in[3];
    const unsigned char* is_first = (const unsigned char*)d_in[4];
    const int*   ens_idx    = (const int*)d_in[5];
    const float* W_gru      = (const float*)d_in[6];
    const float* b_gru      = (const float*)d_in[7];
    const float* ln_g       = (const float*)d_in[8];
    const float* ln_b       = (const float*)d_in[9];
    const float* W_inp      = (const float*)d_in[10];
    const float* b_inp      = (const float*)d_in[11];
    const float* W_obs      = (const float*)d_in[12];
    const float* b_obs      = (const float*)d_in[13];
    const float* W_ens      = (const float*)d_in[14];
    const float* b_ens      = (const float*)d_in[15];
    const float* W_obs_dist = (const float*)d_in[16];
    const float* b_obs_dist = (const float*)d_in[17];
    const float* W_ens_dist = (const float*)d_in[18];
    const float* b_ens_dist = (const float*)d_in[19];
    float* out = (float*)d_out;

    h16 *wgH, *wgL, *woH, *woL, *weH, *weL, *emF, *xF, *dF;
    float *pp1, *php0, *php1, *pxope;
    float *pp0[4], *pxo[4];
    cudaGetSymbolAddress((void**)&wgH, g_WgruH);
    cudaGetSymbolAddress((void**)&wgL, g_WgruL);
    cudaGetSymbolAddress((void**)&woH, g_WobsH);
    cudaGetSymbolAddress((void**)&woL, g_WobsL);
    cudaGetSymbolAddress((void**)&weH, g_WensH);
    cudaGetSymbolAddress((void**)&weL, g_WensL);
    cudaGetSymbolAddress((void**)&emF, g_embF);
    cudaGetSymbolAddress((void**)&xF,  g_xF);
    cudaGetSymbolAddress((void**)&dF,  g_deterF);
    cudaGetSymbolAddress((void**)&pp1, g_pp1);
    cudaGetSymbolAddress((void**)&php0, g_hp0);
    cudaGetSymbolAddress((void**)&php1, g_hp1);
    cudaGetSymbolAddress((void**)&pxope, g_xope);
    {
        float* b0; cudaGetSymbolAddress((void**)&b0, g_pp0);
        float* b1; cudaGetSymbolAddress((void**)&b1, g_xop);
        for (int c = 0; c < 4; c++) {
            pp0[c] = b0 + (size_t)c * B_ * 3072;
            pxo[c] = b1 + (size_t)c * B_ * 1024;
        }
    }

    // persistent streams/events (host objects, created once)
    static cudaStream_t s2 = 0, s3 = 0;
    static cudaEvent_t e0 = 0, eW = 0, eEmb = 0, eTr = 0, eGate = 0,
                       eBg = 0, eFin = 0;
    if (!s2) {
        int lo = 0, hi = 0;
        cudaDeviceGetStreamPriorityRange(&lo, &hi);
        cudaStreamCreateWithPriority(&s2, cudaStreamNonBlocking, lo);
        cudaStreamCreateWithPriority(&s3, cudaStreamNonBlocking, lo);
        cudaEventCreateWithFlags(&e0,    cudaEventDisableTiming);
        cudaEventCreateWithFlags(&eW,    cudaEventDisableTiming);
        cudaEventCreateWithFlags(&eEmb,  cudaEventDisableTiming);
        cudaEventCreateWithFlags(&eTr,   cudaEventDisableTiming);
        cudaEventCreateWithFlags(&eGate, cudaEventDisableTiming);
        cudaEventCreateWithFlags(&eBg,   cudaEventDisableTiming);
        cudaEventCreateWithFlags(&eFin,  cudaEventDisableTiming);
    }

    // sub builders
    auto subGruX = [&](int c) {
        SubTC s = { xF + c * 256, HIDDEN,
                    wgH + (size_t)(c * 256) * 3072, wgL + (size_t)(c * 256) * 3072,
                    3072, 256, 0,
                    c == 0 ? b_gru : nullptr, pp0[c], 3072, 0, 0, 4 };
        return s;
    };
    auto subObsD = [&](int c) {
        SubTC s = { dF + c * 256, DETER,
                    woH + (size_t)(c * 256) * 1024, woL + (size_t)(c * 256) * 1024,
                    1024, 256, 0,
                    c == 0 ? b_obs : nullptr, pxo[c], 1024, 0, 0, 4 };
        return s;
    };
    SubTC subGruD  = { dF, DETER, wgH + (size_t)1024 * 3072,
                       wgL + (size_t)1024 * 3072, 3072, 1024, 0,
                       nullptr, pp1, 3072, 0, 0, 4 };
    SubTC subEns0 = { dF, DETER, weH, weL, 1024, 512, 1,
                      b_ens, php0, 1024, (long long)DETER * HIDDEN, HIDDEN, 4 };
    SubTC subEns1 = { dF + 512, DETER,
                      weH + (size_t)512 * 1024, weL + (size_t)512 * 1024,
                      1024, 512, 1,
                      nullptr, php1, 1024, (long long)DETER * HIDDEN, HIDDEN, 4 };

    // ---- setup: stream 0 ----
    k_init<<<(B_ * DETER + 255) / 256, 256>>>();
    cudaEventRecord(e0, 0);
    k_split<<<4096, 256>>>(W_obs, woH, woL, 2560 * 1024);
    cudaEventRecord(eW, 0);
    k_split<<<4096, 256>>>(W_gru, wgH, wgL, 2048 * 3072);
    k_transpose<<<(6 * 65536) / 256, 256>>>(W_obs_dist, W_ens_dist);
    cudaEventRecord(eTr, 0);
    k_inp0<<<B_, 256>>>(action, is_first, W_inp, b_inp);

    // prologue: gruX(0) (4 chunks) + gruD(0)
    {
        ParamsTC p = {};
        for (int c = 0; c < 4; c++) p.s[c] = subGruX(c);
        for (int i = 0; i <= 4; i++) p.start[i] = i * 192;
        p.nsub = 4;
        gemm_tc<<<768, 128>>>(p, ens_idx, 0);
    }
    {
        ParamsTC p = {};
        p.s[0] = subGruD;
        p.start[0] = 0; p.start[1] = 192;
        p.nsub = 1;
        gemm_tc<<<192, 128>>>(p, ens_idx, 0);
    }

    // ---- s2: embed cast + xope GEMM (setup only) ----
    cudaStreamWaitEvent(s2, e0, 0);
    k_cast<<<8192, 256, 0, s2>>>(embed, emF, B_ * T_ * EMBED);
    cudaStreamWaitEvent(s2, eW, 0);
    {
        ParamsTC p = {};
        p.s[0] = { emF, EMBED,
                   woH + (size_t)1024 * 1024, woL + (size_t)1024 * 1024, 1024,
                   1536, 0, nullptr, pxope, 1024, 0, 0, 256 };
        p.start[0] = 0; p.start[1] = 4096;
        p.nsub = 1;
        gemm_tc<<<4096, 128, 0, s2>>>(p, ens_idx, 0);
    }
    cudaEventRecord(eEmb, s2);

    // ---- s3: Wens split + per-step background ----
    cudaStreamWaitEvent(s3, e0, 0);
    k_split<<<4096, 256, 0, s3>>>(W_ens, weH, weL, ENS * 1024 * 1024);
    cudaStreamWaitEvent(s3, eTr, 0);   // prior needs WedT

    // xope ready before the loop
    cudaStreamWaitEvent(0, eEmb, 0);

    for (int t = 0; t < T_; t++) {
        // gate(t) — needs pp0[0..3] (main) and pp1 (bg, joined via eBg)
        k_gate<<<B_, 256>>>(ln_g, ln_b, is_first, out, t);
        cudaEventRecord(eGate, 0);

        // background (s3): ens(t) [+ gruD(t+1)] GEMM, then prior dist(t)
        cudaStreamWaitEvent(s3, eGate, 0);
        {
            ParamsTC p = {};
            p.s[0] = subEns0;
            p.s[1] = subEns1;
            p.start[0] = 0; p.start[1] = 64; p.start[2] = 128;
            p.nsub = 2;
            int grid = 128;
            if (t + 1 < T_) {
                p.s[2] = subGruD;
                p.start[3] = 320;
                p.nsub = 3;
                grid = 320;
            }
            gemm_tc<<<grid, 128, 0, s3>>>(p, ens_idx, t);
        }
        cudaEventRecord(eBg, s3);
        k_prior<<<B_ / 2, 256, 0, s3>>>(eps_prior, ens_idx, b_ens_dist, out, t);

        // critical: obs-deter GEMM, K split into 4x256 (256 tiles)
        {
            ParamsTC p = {};
            for (int c = 0; c < 4; c++) p.s[c] = subObsD(c);
            for (int i = 0; i <= 4; i++) p.start[i] = i * 64;
            p.nsub = 4;
            gemm_tc<<<256, 128>>>(p, ens_idx, t);
        }

        // posterior + fused inp(t+1)
        k_post_inp<<<B_ / 2, 256>>>(eps_post, b_obs_dist, out,
                                    action, is_first, W_inp, b_inp,
                                    t, t + 1 == T_);

        if (t + 1 < T_) {
            // gruX(t+1): K split into 4x256 (768 tiles)
            ParamsTC p = {};
            for (int c = 0; c < 4; c++) p.s[c] = subGruX(c);
            for (int i = 0; i <= 4; i++) p.start[i] = i * 192;
            p.nsub = 4;
            gemm_tc<<<768, 128>>>(p, ens_idx, t + 1);
            cudaStreamWaitEvent(0, eBg, 0);   // pp1 ready before gate(t+1)
        }
    }

    // final join: all background work before harness reads
    cudaEventRecord(eFin, s3);
    cudaStreamWaitEvent(0, eFin, 0);
}